// round 2
// baseline (speedup 1.0000x reference)
#include <cuda_runtime.h>
#include <math.h>

#define NN 50000
#define HH 256
#define NE 300000
#define H3 (3*HH)

// ---------------- scratch (static device globals; allocation-free) ----------
__device__ float g_h0[NN*HH];
__device__ float g_h1[NN*HH];
__device__ float g_m [NN*HH];
__device__ float g_agg[NN*HH];
__device__ float g_gi[(size_t)NN*H3];
__device__ float g_gh[(size_t)NN*H3];

// ---------------- GEMM: C[M,N] = A[M,K] @ B + bias ------------------------
// BT=false: B is [K,N] row-major (B[k*N+n])
// BT=true : B is W [N,K] row-major (C = A @ W^T)
#define BM 128
#define BN 128
#define BK 8

template<bool BT>
__global__ __launch_bounds__(256, 2)
void sgemm_kernel(const float* __restrict__ A, const float* __restrict__ B,
                  const float* __restrict__ bias, float* __restrict__ C,
                  int M, int N, int K)
{
    __shared__ float Asd[BK][2*BM];   // A duplicated: Asd[k][2r]=Asd[k][2r+1]=A[r][k]
    __shared__ float Bs [BK][BN];

    const int tid = threadIdx.x;
    const int tx = tid & 15;          // 16 col-threads
    const int ty = tid >> 4;          // 16 row-threads
    const int bm = blockIdx.y * BM;
    const int bn = blockIdx.x * BN;

    // A tile loader: thread -> row tid/2, 4 consecutive k at (tid&1)*4
    const int arow = tid >> 1;
    const int acol = (tid & 1) * 4;

    unsigned long long acc[8][4];
    #pragma unroll
    for (int i = 0; i < 8; i++)
        #pragma unroll
        for (int j = 0; j < 4; j++) acc[i][j] = 0ull;

    for (int k0 = 0; k0 < K; k0 += BK) {
        // ---- load A tile (with M guard), store duplicated ----
        float4 av;
        int gr = bm + arow;
        if (gr < M) av = *(const float4*)(A + (size_t)gr*K + k0 + acol);
        else        av = make_float4(0.f,0.f,0.f,0.f);
        Asd[acol+0][2*arow] = av.x; Asd[acol+0][2*arow+1] = av.x;
        Asd[acol+1][2*arow] = av.y; Asd[acol+1][2*arow+1] = av.y;
        Asd[acol+2][2*arow] = av.z; Asd[acol+2][2*arow+1] = av.z;
        Asd[acol+3][2*arow] = av.w; Asd[acol+3][2*arow+1] = av.w;

        // ---- load B tile ----
        if (BT) {
            int nr = tid >> 1;
            int kc = (tid & 1) * 4;
            float4 bv = *(const float4*)(B + (size_t)(bn + nr)*K + k0 + kc);
            Bs[kc+0][nr] = bv.x; Bs[kc+1][nr] = bv.y;
            Bs[kc+2][nr] = bv.z; Bs[kc+3][nr] = bv.w;
        } else {
            int kr = tid >> 5;
            int nc = (tid & 31) * 4;
            float4 bv = *(const float4*)(B + (size_t)(k0 + kr)*N + bn + nc);
            *(float4*)&Bs[kr][nc] = bv;
        }
        __syncthreads();

        // ---- packed f32x2 inner loop: 32 FMA2 per k per thread ----
        #pragma unroll
        for (int k = 0; k < BK; k++) {
            unsigned long long ad[8], bp[4];
            #pragma unroll
            for (int i = 0; i < 8; i++)
                ad[i] = *(const unsigned long long*)&Asd[k][2*(ty*8 + i)];
            #pragma unroll
            for (int j = 0; j < 4; j++)
                bp[j] = *(const unsigned long long*)&Bs[k][tx*8 + 2*j];
            #pragma unroll
            for (int i = 0; i < 8; i++)
                #pragma unroll
                for (int j = 0; j < 4; j++)
                    asm("fma.rn.f32x2 %0, %1, %2, %0;"
                        : "+l"(acc[i][j]) : "l"(ad[i]), "l"(bp[j]));
        }
        __syncthreads();
    }

    // ---- epilogue ----
    #pragma unroll
    for (int i = 0; i < 8; i++) {
        int r = bm + ty*8 + i;
        if (r >= M) continue;
        float v[8];
        #pragma unroll
        for (int j = 0; j < 4; j++) {
            unsigned int lo, hi;
            asm("mov.b64 {%0,%1}, %2;" : "=r"(lo), "=r"(hi) : "l"(acc[i][j]));
            v[2*j]   = __uint_as_float(lo);
            v[2*j+1] = __uint_as_float(hi);
        }
        int cbase = bn + tx*8;
        if (bias) {
            #pragma unroll
            for (int j = 0; j < 8; j++) v[j] += bias[cbase + j];
        }
        float4 s0 = make_float4(v[0],v[1],v[2],v[3]);
        float4 s1 = make_float4(v[4],v[5],v[6],v[7]);
        *(float4*)(C + (size_t)r*N + cbase)     = s0;
        *(float4*)(C + (size_t)r*N + cbase + 4) = s1;
    }
}

// ---------------- zero -------------------------------------------------------
__global__ void zero_kernel(float4* __restrict__ p, int n4) {
    int t = blockIdx.x * blockDim.x + threadIdx.x;
    if (t < n4) p[t] = make_float4(0.f,0.f,0.f,0.f);
}

// ---------------- edge scatter: agg[dst] += m[src] ---------------------------
// 64 threads per edge, each handles 4 consecutive floats.
__global__ void scatter_kernel(const float* __restrict__ m,
                               const int* __restrict__ src,
                               const int* __restrict__ dst,
                               float* __restrict__ agg)
{
    long long t = (long long)blockIdx.x * blockDim.x + threadIdx.x;
    int e = (int)(t >> 6);
    if (e >= NE) return;
    int c = ((int)t & 63) << 2;
    int s = __ldg(src + e);
    int d = __ldg(dst + e);
    float4 v = *(const float4*)(m + (size_t)s*HH + c);
    float* p = agg + (size_t)d*HH + c;
    asm volatile("red.global.add.v4.f32 [%0], {%1,%2,%3,%4};"
                 :: "l"(p), "f"(v.x), "f"(v.y), "f"(v.z), "f"(v.w) : "memory");
}

// ---------------- GRU elementwise -------------------------------------------
__device__ __forceinline__ float gru1(float ir, float hr, float iz, float hz,
                                      float in_, float hn_, float h)
{
    float r  = 1.f / (1.f + __expf(-(ir + hr)));
    float z  = 1.f / (1.f + __expf(-(iz + hz)));
    float nn = tanhf(in_ + r * hn_);
    return (1.f - z) * nn + z * h;
}

__global__ void gru_kernel(const float* __restrict__ gi, const float* __restrict__ gh,
                           const float* __restrict__ h, float* __restrict__ hn)
{
    int t = blockIdx.x * blockDim.x + threadIdx.x;
    if (t >= NN * (HH/4)) return;
    int i = t >> 6;
    int c = (t & 63) << 2;
    size_t b3 = (size_t)i * H3 + c;
    size_t b1 = (size_t)i * HH + c;
    float4 ir  = *(const float4*)(gi + b3);
    float4 hr  = *(const float4*)(gh + b3);
    float4 iz  = *(const float4*)(gi + b3 + HH);
    float4 hz  = *(const float4*)(gh + b3 + HH);
    float4 in_ = *(const float4*)(gi + b3 + 2*HH);
    float4 hn_ = *(const float4*)(gh + b3 + 2*HH);
    float4 hv  = *(const float4*)(h + b1);
    float4 o;
    o.x = gru1(ir.x, hr.x, iz.x, hz.x, in_.x, hn_.x, hv.x);
    o.y = gru1(ir.y, hr.y, iz.y, hz.y, in_.y, hn_.y, hv.y);
    o.z = gru1(ir.z, hr.z, iz.z, hz.z, in_.z, hn_.z, hv.z);
    o.w = gru1(ir.w, hr.w, iz.w, hz.w, in_.w, hn_.w, hv.w);
    *(float4*)(hn + b1) = o;
}

// ---------------- head: relu(h) @ W_lin^T + b, log_softmax -------------------
__global__ void head_kernel(const float* __restrict__ h,
                            const float* __restrict__ W_lin,
                            const float* __restrict__ b_lin,
                            float* __restrict__ out)
{
    int gw = (blockIdx.x * blockDim.x + threadIdx.x) >> 5;
    int lane = threadIdx.x & 31;
    if (gw >= NN) return;
    const float* hr = h + (size_t)gw * HH;
    float a0 = 0.f, a1 = 0.f;
    #pragma unroll
    for (int k = lane; k < HH; k += 32) {
        float v = hr[k];
        v = v > 0.f ? v : 0.f;
        a0 += v * __ldg(W_lin + k);
        a1 += v * __ldg(W_lin + HH + k);
    }
    #pragma unroll
    for (int off = 16; off; off >>= 1) {
        a0 += __shfl_xor_sync(0xffffffffu, a0, off);
        a1 += __shfl_xor_sync(0xffffffffu, a1, off);
    }
    if (lane == 0) {
        float o0 = a0 + b_lin[0];
        float o1 = a1 + b_lin[1];
        float mx = fmaxf(o0, o1);
        float lse = mx + logf(expf(o0 - mx) + expf(o1 - mx));
        out[2*gw]     = o0 - lse;
        out[2*gw + 1] = o1 - lse;
    }
}

// ---------------- launch -----------------------------------------------------
extern "C" void kernel_launch(void* const* d_in, const int* in_sizes, int n_in,
                              void* d_out, int out_size)
{
    const float* x        = (const float*)d_in[0];
    const int*   edge     = (const int*)  d_in[1];
    // d_in[2] = batch (unused)
    const float* W_reduce = (const float*)d_in[3];
    const float* b_reduce = (const float*)d_in[4];
    const float* W_ggc    = (const float*)d_in[5];
    const float* W_ih     = (const float*)d_in[6];
    const float* W_hh     = (const float*)d_in[7];
    const float* b_ih     = (const float*)d_in[8];
    const float* b_hh     = (const float*)d_in[9];
    const float* W_lin    = (const float*)d_in[10];
    const float* b_lin    = (const float*)d_in[11];
    float* out = (float*)d_out;

    const int* src = edge;        // edge_index[0]
    const int* dst = edge + NE;   // edge_index[1]

    float *h0, *h1, *mbuf, *agg, *gi, *gh;
    cudaGetSymbolAddress((void**)&h0,   g_h0);
    cudaGetSymbolAddress((void**)&h1,   g_h1);
    cudaGetSymbolAddress((void**)&mbuf, g_m);
    cudaGetSymbolAddress((void**)&agg,  g_agg);
    cudaGetSymbolAddress((void**)&gi,   g_gi);
    cudaGetSymbolAddress((void**)&gh,   g_gh);

    const int mtiles = (NN + BM - 1) / BM;   // 391

    // h = x @ W_reduce^T + b_reduce
    sgemm_kernel<true><<<dim3(HH/BN, mtiles), 256>>>(x, W_reduce, b_reduce, h0, NN, HH, 200);

    float* hc = h0;
    float* hn = h1;
    for (int s = 0; s < 8; s++) {
        // m = h @ W_ggc[s]
        sgemm_kernel<false><<<dim3(HH/BN, mtiles), 256>>>(hc, W_ggc + (size_t)s*HH*HH, nullptr, mbuf, NN, HH, HH);
        // agg = 0 ; agg[dst] += m[src]
        zero_kernel<<<(NN*HH/4 + 255)/256, 256>>>((float4*)agg, NN*HH/4);
        scatter_kernel<<<((long long)NE*64 + 255)/256, 256>>>(mbuf, src, dst, agg);
        // gi = agg @ W_ih^T + b_ih ; gh = h @ W_hh^T + b_hh
        sgemm_kernel<true><<<dim3(H3/BN, mtiles), 256>>>(agg, W_ih, b_ih, gi, NN, H3, HH);
        sgemm_kernel<true><<<dim3(H3/BN, mtiles), 256>>>(hc,  W_hh, b_hh, gh, NN, H3, HH);
        // GRU
        gru_kernel<<<(NN*(HH/4) + 255)/256, 256>>>(gi, gh, hc, hn);
        float* t = hc; hc = hn; hn = t;
    }

    head_kernel<<<(NN*32 + 255)/256, 256>>>(hc, W_lin, b_lin, out);
}

// round 5
// speedup vs baseline: 2.3646x; 2.3646x over previous
#include <cuda_runtime.h>
#include <cuda_bf16.h>
#include <math.h>
#include <stdint.h>

#define NN 50000
#define HH 256
#define NE 300000
#define H3 (3*HH)
#define KP 256   // padded K for all GEMMs

// ---------------- scratch (static device globals; allocation-free) ----------
__device__ float g_h0[NN*HH];
__device__ float g_h1[NN*HH];
__device__ float g_m [NN*HH];
__device__ float g_agg[NN*HH];
__device__ float g_gi[(size_t)NN*H3];
__device__ float g_gh[(size_t)NN*H3];

// bf16 split weights, [N, 256] K-major row-major
__device__ __nv_bfloat16 g_wred_hi[HH*KP],    g_wred_lo[HH*KP];
__device__ __nv_bfloat16 g_wggc_hi[8*HH*KP],  g_wggc_lo[8*HH*KP];
__device__ __nv_bfloat16 g_wih_hi[H3*KP],     g_wih_lo[H3*KP];
__device__ __nv_bfloat16 g_whh_hi[H3*KP],     g_whh_lo[H3*KP];

// ---------------- weight conversion ----------------------------------------
__global__ void conv_w(const float* __restrict__ W, __nv_bfloat16* __restrict__ hi,
                       __nv_bfloat16* __restrict__ lo, int Nrows, int Ksrc)
{
    int t = blockIdx.x * blockDim.x + threadIdx.x;
    if (t >= Nrows * KP) return;
    int n = t >> 8, k = t & 255;
    float v = (k < Ksrc) ? W[(size_t)n * Ksrc + k] : 0.f;
    __nv_bfloat16 h = __float2bfloat16(v);
    hi[t] = h;
    lo[t] = __float2bfloat16(v - __bfloat162float(h));
}

// W_ggc [8,K,N] -> transposed [8,N,K]
__global__ void conv_wggcT(const float* __restrict__ W, __nv_bfloat16* __restrict__ hi,
                           __nv_bfloat16* __restrict__ lo)
{
    int t = blockIdx.x * blockDim.x + threadIdx.x;
    if (t >= 8 * HH * KP) return;
    int s = t >> 16, n = (t >> 8) & 255, k = t & 255;
    float v = W[((size_t)s << 16) + (size_t)k * HH + n];
    __nv_bfloat16 h = __float2bfloat16(v);
    hi[t] = h;
    lo[t] = __float2bfloat16(v - __bfloat162float(h));
}

// ---------------- helpers ----------------------------------------------------
__device__ __forceinline__ uint32_t smem_u32(const void* p) {
    uint32_t a;
    asm("{ .reg .u64 t; cvta.to.shared.u64 t, %1; cvt.u32.u64 %0, t; }" : "=r"(a) : "l"(p));
    return a;
}

__device__ __forceinline__ void ldmx4(uint32_t* r, uint32_t addr) {
    asm volatile("ldmatrix.sync.aligned.m8n8.x4.shared.b16 {%0,%1,%2,%3}, [%4];"
                 : "=r"(r[0]), "=r"(r[1]), "=r"(r[2]), "=r"(r[3]) : "r"(addr));
}

__device__ __forceinline__ void mma16816(float* d, const uint32_t* a, uint32_t b0, uint32_t b1) {
    asm volatile(
        "mma.sync.aligned.m16n8k16.row.col.f32.bf16.bf16.f32 "
        "{%0,%1,%2,%3}, {%4,%5,%6,%7}, {%8,%9}, {%0,%1,%2,%3};"
        : "+f"(d[0]), "+f"(d[1]), "+f"(d[2]), "+f"(d[3])
        : "r"(a[0]), "r"(a[1]), "r"(a[2]), "r"(a[3]), "r"(b0), "r"(b1));
}

// ---------------- GEMM: C[M,N] = A(fp32)[M,Ksrc<=256] @ B(bf16 hi/lo)[N,256]^T + bias
// block 128x128, 8 warps (4 in M x 2 in N), warp tile 32x64, K-chunk 32.
#define LDS 40   // smem row stride in bf16 (32 data + 8 pad)

__global__ __launch_bounds__(256)
void mma_gemm(const float* __restrict__ A,
              const __nv_bfloat16* __restrict__ Bhi,
              const __nv_bfloat16* __restrict__ Blo,
              const float* __restrict__ bias,
              float* __restrict__ C, int M, int N, int Ksrc)
{
    __shared__ __nv_bfloat16 sAhi[128*LDS], sAlo[128*LDS];
    __shared__ __nv_bfloat16 sBhi[128*LDS], sBlo[128*LDS];

    const int tid = threadIdx.x;
    const int lane = tid & 31, wid = tid >> 5;
    const int bm = blockIdx.y * 128, bn = blockIdx.x * 128;
    const int wm = (wid & 3) * 32, wn = (wid >> 2) * 64;

    float c[2][8][4];
    #pragma unroll
    for (int i = 0; i < 2; i++)
        #pragma unroll
        for (int j = 0; j < 8; j++)
            #pragma unroll
            for (int q = 0; q < 4; q++) c[i][j][q] = 0.f;

    // loader mapping: each thread handles one row (tid>>1), 16 cols at (tid&1)*16
    const int lrow = tid >> 1;
    const int lcol = (tid & 1) * 16;
    const bool rv = (bm + lrow) < M;
    const float* Arow = A + (size_t)(bm + lrow) * Ksrc + lcol;
    const __nv_bfloat16* Bh = Bhi + (size_t)(bn + lrow) * KP + lcol;
    const __nv_bfloat16* Bl = Blo + (size_t)(bn + lrow) * KP + lcol;

    // ldmatrix per-thread row/col offsets
    const int aro = (lane & 7) + ((lane >> 3) & 1) * 8;   // A: row within m16
    const int ako = ((lane >> 4) & 1) * 8;                // A: k offset
    const int bro = (lane & 7) + ((lane >> 4) & 1) * 8;   // B: row (n) within n16
    const int bko = ((lane >> 3) & 1) * 8;                // B: k offset

    const uint32_t uAhi = smem_u32(sAhi), uAlo = smem_u32(sAlo);
    const uint32_t uBhi = smem_u32(sBhi), uBlo = smem_u32(sBlo);

    for (int ch = 0; ch < 8; ch++) {
        const int k0 = ch * 32;
        // ---- A chunk: fp32 -> bf16 hi/lo into smem ----
        #pragma unroll
        for (int q = 0; q < 4; q++) {
            int k = k0 + lcol + q * 4;
            float4 v = make_float4(0.f, 0.f, 0.f, 0.f);
            if (rv && k < Ksrc) v = *(const float4*)(Arow + k0 + q * 4);
            __nv_bfloat162 hxy, hzw, lxy, lzw;
            hxy.x = __float2bfloat16(v.x); hxy.y = __float2bfloat16(v.y);
            hzw.x = __float2bfloat16(v.z); hzw.y = __float2bfloat16(v.w);
            lxy.x = __float2bfloat16(v.x - __bfloat162float(hxy.x));
            lxy.y = __float2bfloat16(v.y - __bfloat162float(hxy.y));
            lzw.x = __float2bfloat16(v.z - __bfloat162float(hzw.x));
            lzw.y = __float2bfloat16(v.w - __bfloat162float(hzw.y));
            int o = lrow * LDS + lcol + q * 4;
            *(__nv_bfloat162*)&sAhi[o]     = hxy;
            *(__nv_bfloat162*)&sAhi[o + 2] = hzw;
            *(__nv_bfloat162*)&sAlo[o]     = lxy;
            *(__nv_bfloat162*)&sAlo[o + 2] = lzw;
        }
        // ---- B chunk: bf16 copy into smem ----
        {
            int o = lrow * LDS + lcol;
            uint4 v0 = *(const uint4*)(Bh + k0);
            uint4 v1 = *(const uint4*)(Bh + k0 + 8);
            *(uint4*)&sBhi[o]     = v0;
            *(uint4*)&sBhi[o + 8] = v1;
            uint4 w0 = *(const uint4*)(Bl + k0);
            uint4 w1 = *(const uint4*)(Bl + k0 + 8);
            *(uint4*)&sBlo[o]     = w0;
            *(uint4*)&sBlo[o + 8] = w1;
        }
        __syncthreads();

        // ---- compute: 2 k16 halves ----
        #pragma unroll
        for (int kh = 0; kh < 2; kh++) {
            const int kb = kh * 16;
            uint32_t ah[2][4], al[2][4];
            #pragma unroll
            for (int mt = 0; mt < 2; mt++) {
                uint32_t off = (uint32_t)(((wm + mt * 16 + aro) * LDS + kb + ako) * 2);
                ldmx4(ah[mt], uAhi + off);
                ldmx4(al[mt], uAlo + off);
            }
            #pragma unroll
            for (int ng = 0; ng < 4; ng++) {
                uint32_t bh[4], bl[4];
                uint32_t off = (uint32_t)(((wn + ng * 16 + bro) * LDS + kb + bko) * 2);
                ldmx4(bh, uBhi + off);
                ldmx4(bl, uBlo + off);
                #pragma unroll
                for (int mt = 0; mt < 2; mt++) {
                    mma16816(c[mt][2*ng],   ah[mt], bh[0], bh[1]);
                    mma16816(c[mt][2*ng+1], ah[mt], bh[2], bh[3]);
                    mma16816(c[mt][2*ng],   ah[mt], bl[0], bl[1]);
                    mma16816(c[mt][2*ng+1], ah[mt], bl[2], bl[3]);
                    mma16816(c[mt][2*ng],   al[mt], bh[0], bh[1]);
                    mma16816(c[mt][2*ng+1], al[mt], bh[2], bh[3]);
                }
            }
        }
        __syncthreads();
    }

    // ---- epilogue ----
    #pragma unroll
    for (int mt = 0; mt < 2; mt++) {
        int row = bm + wm + mt * 16 + (lane >> 2);
        #pragma unroll
        for (int nidx = 0; nidx < 8; nidx++) {
            int col = bn + wn + nidx * 8 + (lane & 3) * 2;
            float b0 = 0.f, b1 = 0.f;
            if (bias) { b0 = bias[col]; b1 = bias[col + 1]; }
            if (row < M) {
                float2 v = make_float2(c[mt][nidx][0] + b0, c[mt][nidx][1] + b1);
                *(float2*)(C + (size_t)row * N + col) = v;
            }
            if (row + 8 < M) {
                float2 v = make_float2(c[mt][nidx][2] + b0, c[mt][nidx][3] + b1);
                *(float2*)(C + (size_t)(row + 8) * N + col) = v;
            }
        }
    }
}

// ---------------- zero -------------------------------------------------------
__global__ void zero_kernel(float4* __restrict__ p, int n4) {
    int t = blockIdx.x * blockDim.x + threadIdx.x;
    if (t < n4) p[t] = make_float4(0.f, 0.f, 0.f, 0.f);
}

// ---------------- edge scatter: agg[dst] += m[src] ---------------------------
__global__ void scatter_kernel(const float* __restrict__ m,
                               const int* __restrict__ src,
                               const int* __restrict__ dst,
                               float* __restrict__ agg)
{
    long long t = (long long)blockIdx.x * blockDim.x + threadIdx.x;
    int e = (int)(t >> 6);
    if (e >= NE) return;
    int c = ((int)t & 63) << 2;
    int s = __ldg(src + e);
    int d = __ldg(dst + e);
    float4 v = *(const float4*)(m + (size_t)s * HH + c);
    float* p = agg + (size_t)d * HH + c;
    asm volatile("red.global.add.v4.f32 [%0], {%1,%2,%3,%4};"
                 :: "l"(p), "f"(v.x), "f"(v.y), "f"(v.z), "f"(v.w) : "memory");
}

// ---------------- GRU elementwise -------------------------------------------
__device__ __forceinline__ float gru1(float ir, float hr, float iz, float hz,
                                      float in_, float hn_, float h)
{
    float r  = 1.f / (1.f + __expf(-(ir + hr)));
    float z  = 1.f / (1.f + __expf(-(iz + hz)));
    float nn = tanhf(in_ + r * hn_);
    return (1.f - z) * nn + z * h;
}

__global__ void gru_kernel(const float* __restrict__ gi, const float* __restrict__ gh,
                           const float* __restrict__ h, float* __restrict__ hn)
{
    int t = blockIdx.x * blockDim.x + threadIdx.x;
    if (t >= NN * (HH/4)) return;
    int i = t >> 6;
    int c = (t & 63) << 2;
    size_t b3 = (size_t)i * H3 + c;
    size_t b1 = (size_t)i * HH + c;
    float4 ir  = *(const float4*)(gi + b3);
    float4 hr  = *(const float4*)(gh + b3);
    float4 iz  = *(const float4*)(gi + b3 + HH);
    float4 hz  = *(const float4*)(gh + b3 + HH);
    float4 in_ = *(const float4*)(gi + b3 + 2*HH);
    float4 hn_ = *(const float4*)(gh + b3 + 2*HH);
    float4 hv  = *(const float4*)(h + b1);
    float4 o;
    o.x = gru1(ir.x, hr.x, iz.x, hz.x, in_.x, hn_.x, hv.x);
    o.y = gru1(ir.y, hr.y, iz.y, hz.y, in_.y, hn_.y, hv.y);
    o.z = gru1(ir.z, hr.z, iz.z, hz.z, in_.z, hn_.z, hv.z);
    o.w = gru1(ir.w, hr.w, iz.w, hz.w, in_.w, hn_.w, hv.w);
    *(float4*)(hn + b1) = o;
}

// ---------------- head: relu(h) @ W_lin^T + b, log_softmax -------------------
__global__ void head_kernel(const float* __restrict__ h,
                            const float* __restrict__ W_lin,
                            const float* __restrict__ b_lin,
                            float* __restrict__ out)
{
    int gw = (blockIdx.x * blockDim.x + threadIdx.x) >> 5;
    int lane = threadIdx.x & 31;
    if (gw >= NN) return;
    const float* hr = h + (size_t)gw * HH;
    float a0 = 0.f, a1 = 0.f;
    #pragma unroll
    for (int k = lane; k < HH; k += 32) {
        float v = hr[k];
        v = v > 0.f ? v : 0.f;
        a0 += v * __ldg(W_lin + k);
        a1 += v * __ldg(W_lin + HH + k);
    }
    #pragma unroll
    for (int off = 16; off; off >>= 1) {
        a0 += __shfl_xor_sync(0xffffffffu, a0, off);
        a1 += __shfl_xor_sync(0xffffffffu, a1, off);
    }
    if (lane == 0) {
        float o0 = a0 + b_lin[0];
        float o1 = a1 + b_lin[1];
        float mx = fmaxf(o0, o1);
        float lse = mx + logf(expf(o0 - mx) + expf(o1 - mx));
        out[2*gw]     = o0 - lse;
        out[2*gw + 1] = o1 - lse;
    }
}

// ---------------- launch -----------------------------------------------------
extern "C" void kernel_launch(void* const* d_in, const int* in_sizes, int n_in,
                              void* d_out, int out_size)
{
    const float* x        = (const float*)d_in[0];
    const int*   edge     = (const int*)  d_in[1];
    const float* W_reduce = (const float*)d_in[3];
    const float* b_reduce = (const float*)d_in[4];
    const float* W_ggc    = (const float*)d_in[5];
    const float* W_ih     = (const float*)d_in[6];
    const float* W_hh     = (const float*)d_in[7];
    const float* b_ih     = (const float*)d_in[8];
    const float* b_hh     = (const float*)d_in[9];
    const float* W_lin    = (const float*)d_in[10];
    const float* b_lin    = (const float*)d_in[11];
    float* out = (float*)d_out;

    const int* src = edge;
    const int* dst = edge + NE;

    float *h0, *h1, *mbuf, *agg, *gi, *gh;
    cudaGetSymbolAddress((void**)&h0,   g_h0);
    cudaGetSymbolAddress((void**)&h1,   g_h1);
    cudaGetSymbolAddress((void**)&mbuf, g_m);
    cudaGetSymbolAddress((void**)&agg,  g_agg);
    cudaGetSymbolAddress((void**)&gi,   g_gi);
    cudaGetSymbolAddress((void**)&gh,   g_gh);

    __nv_bfloat16 *wred_h, *wred_l, *wggc_h, *wggc_l, *wih_h, *wih_l, *whh_h, *whh_l;
    cudaGetSymbolAddress((void**)&wred_h, g_wred_hi);
    cudaGetSymbolAddress((void**)&wred_l, g_wred_lo);
    cudaGetSymbolAddress((void**)&wggc_h, g_wggc_hi);
    cudaGetSymbolAddress((void**)&wggc_l, g_wggc_lo);
    cudaGetSymbolAddress((void**)&wih_h,  g_wih_hi);
    cudaGetSymbolAddress((void**)&wih_l,  g_wih_lo);
    cudaGetSymbolAddress((void**)&whh_h,  g_whh_hi);
    cudaGetSymbolAddress((void**)&whh_l,  g_whh_lo);

    // weight conversions (per launch, deterministic)
    conv_w<<<(HH*KP + 255)/256, 256>>>(W_reduce, wred_h, wred_l, HH, 200);
    conv_w<<<(H3*KP + 255)/256, 256>>>(W_ih, wih_h, wih_l, H3, KP);
    conv_w<<<(H3*KP + 255)/256, 256>>>(W_hh, whh_h, whh_l, H3, KP);
    conv_wggcT<<<(8*HH*KP + 255)/256, 256>>>(W_ggc, wggc_h, wggc_l);

    const int mtiles = (NN + 127) / 128;   // 391

    // h = x @ W_reduce^T + b_reduce
    mma_gemm<<<dim3(HH/128, mtiles), 256>>>(x, wred_h, wred_l, b_reduce, h0, NN, HH, 200);

    float* hc = h0;
    float* hn = h1;
    for (int s = 0; s < 8; s++) {
        mma_gemm<<<dim3(HH/128, mtiles), 256>>>(hc, wggc_h + (size_t)s*HH*KP,
                                                wggc_l + (size_t)s*HH*KP,
                                                nullptr, mbuf, NN, HH, KP);
        zero_kernel<<<(NN*HH/4 + 255)/256, 256>>>((float4*)agg, NN*HH/4);
        scatter_kernel<<<((long long)NE*64 + 255)/256, 256>>>(mbuf, src, dst, agg);
        mma_gemm<<<dim3(H3/128, mtiles), 256>>>(agg, wih_h, wih_l, b_ih, gi, NN, H3, KP);
        mma_gemm<<<dim3(H3/128, mtiles), 256>>>(hc,  whh_h, whh_l, b_hh, gh, NN, H3, KP);
        gru_kernel<<<(NN*(HH/4) + 255)/256, 256>>>(gi, gh, hc, hn);
        float* t = hc; hc = hn; hn = t;
    }

    head_kernel<<<(NN*32 + 255)/256, 256>>>(hc, W_lin, b_lin, out);
}

// round 6
// speedup vs baseline: 2.4235x; 1.0249x over previous
#include <cuda_runtime.h>
#include <cuda_bf16.h>
#include <math.h>
#include <stdint.h>

#define NN 50000
#define HH 256
#define NE 300000
#define H3 (3*HH)
#define KP 256   // padded K for all GEMMs

// ---------------- scratch (static device globals; allocation-free) ----------
__device__ float g_h0[NN*HH];
__device__ float g_h1[NN*HH];
__device__ float g_m [NN*HH];
__device__ float g_agg[NN*HH];
__device__ float g_gi[(size_t)NN*H3];
__device__ float g_gh[(size_t)NN*H3];

// bf16 split weights, [N, 256] K-major row-major
__device__ __nv_bfloat16 g_wred_hi[HH*KP],    g_wred_lo[HH*KP];
__device__ __nv_bfloat16 g_wggc_hi[8*HH*KP],  g_wggc_lo[8*HH*KP];
__device__ __nv_bfloat16 g_wih_hi[H3*KP],     g_wih_lo[H3*KP];
__device__ __nv_bfloat16 g_whh_hi[H3*KP],     g_whh_lo[H3*KP];

// ---------------- weight conversion ----------------------------------------
__global__ void conv_w(const float* __restrict__ W, __nv_bfloat16* __restrict__ hi,
                       __nv_bfloat16* __restrict__ lo, int Nrows, int Ksrc)
{
    int t = blockIdx.x * blockDim.x + threadIdx.x;
    if (t >= Nrows * KP) return;
    int n = t >> 8, k = t & 255;
    float v = (k < Ksrc) ? W[(size_t)n * Ksrc + k] : 0.f;
    __nv_bfloat16 h = __float2bfloat16(v);
    hi[t] = h;
    lo[t] = __float2bfloat16(v - __bfloat162float(h));
}

// W_ggc [8,K,N] -> transposed [8,N,K]
__global__ void conv_wggcT(const float* __restrict__ W, __nv_bfloat16* __restrict__ hi,
                           __nv_bfloat16* __restrict__ lo)
{
    int t = blockIdx.x * blockDim.x + threadIdx.x;
    if (t >= 8 * HH * KP) return;
    int s = t >> 16, n = (t >> 8) & 255, k = t & 255;
    float v = W[((size_t)s << 16) + (size_t)k * HH + n];
    __nv_bfloat16 h = __float2bfloat16(v);
    hi[t] = h;
    lo[t] = __float2bfloat16(v - __bfloat162float(h));
}

// ---------------- helpers ----------------------------------------------------
__device__ __forceinline__ uint32_t smem_u32(const void* p) {
    uint32_t a;
    asm("{ .reg .u64 t; cvta.to.shared.u64 t, %1; cvt.u32.u64 %0, t; }" : "=r"(a) : "l"(p));
    return a;
}

__device__ __forceinline__ void ldmx4(uint32_t* r, uint32_t addr) {
    asm volatile("ldmatrix.sync.aligned.m8n8.x4.shared.b16 {%0,%1,%2,%3}, [%4];"
                 : "=r"(r[0]), "=r"(r[1]), "=r"(r[2]), "=r"(r[3]) : "r"(addr));
}

__device__ __forceinline__ void mma16816(float* d, const uint32_t* a, uint32_t b0, uint32_t b1) {
    asm volatile(
        "mma.sync.aligned.m16n8k16.row.col.f32.bf16.bf16.f32 "
        "{%0,%1,%2,%3}, {%4,%5,%6,%7}, {%8,%9}, {%0,%1,%2,%3};"
        : "+f"(d[0]), "+f"(d[1]), "+f"(d[2]), "+f"(d[3])
        : "r"(a[0]), "r"(a[1]), "r"(a[2]), "r"(a[3]), "r"(b0), "r"(b1));
}

__device__ __forceinline__ void cpa16(uint32_t dst, const void* src) {
    asm volatile("cp.async.ca.shared.global [%0], [%1], 16;" :: "r"(dst), "l"(src) : "memory");
}
__device__ __forceinline__ void cpa_commit() {
    asm volatile("cp.async.commit_group;" ::: "memory");
}

// ---------------- GEMM: C[M,N] = A(fp32)[M,Ksrc<=256] @ B(bf16 hi/lo)[N,256]^T + bias
// block 128x128, 8 warps (4 in M x 2 in N), warp tile 32x64, K-chunk 32.
// Two-stage software pipeline: B via cp.async, A via register prefetch+convert.
#define LDS 40                      // smem row stride in bf16 (32 data + 8 pad)
#define ARR (128*LDS)               // elems per array
#define STG (4*ARR)                 // elems per stage (Ahi, Alo, Bhi, Blo)
#define SMEM_BYTES (2*STG*2)

__global__ __launch_bounds__(256)
void mma_gemm(const float* __restrict__ A,
              const __nv_bfloat16* __restrict__ Bhi,
              const __nv_bfloat16* __restrict__ Blo,
              const float* __restrict__ bias,
              float* __restrict__ C, int M, int N, int Ksrc)
{
    extern __shared__ __nv_bfloat16 smp[];

    const int tid = threadIdx.x;
    const int lane = tid & 31, wid = tid >> 5;
    const int bm = blockIdx.y * 128, bn = blockIdx.x * 128;
    const int wm = (wid & 3) * 32, wn = (wid >> 2) * 64;

    float c[2][8][4];
    #pragma unroll
    for (int i = 0; i < 2; i++)
        #pragma unroll
        for (int j = 0; j < 8; j++)
            #pragma unroll
            for (int q = 0; q < 4; q++) c[i][j][q] = 0.f;

    // loader mapping: row = tid>>1 (0..127), 16 cols at (tid&1)*16
    const int lrow = tid >> 1;
    const int lcol = (tid & 1) * 16;
    const bool rv = (bm + lrow) < M;
    const float* Arow = A + (size_t)(bm + lrow) * Ksrc + lcol;
    const __nv_bfloat16* Bh = Bhi + (size_t)(bn + lrow) * KP + lcol;
    const __nv_bfloat16* Bl = Blo + (size_t)(bn + lrow) * KP + lcol;

    const uint32_t u0 = smem_u32(smp);
    const int lodst = lrow * LDS + lcol;                 // elem offset within array
    const uint32_t bdst_h = u0 + (uint32_t)(2*ARR + lodst) * 2;  // Bhi byte offset in stage
    const uint32_t bdst_l = u0 + (uint32_t)(3*ARR + lodst) * 2;

    // ldmatrix per-thread row/col offsets
    const int aro = (lane & 7) + ((lane >> 3) & 1) * 8;
    const int ako = ((lane >> 4) & 1) * 8;
    const int bro = (lane & 7) + ((lane >> 4) & 1) * 8;
    const int bko = ((lane >> 3) & 1) * 8;

    float ar[16];

    // ---- prologue: chunk 0 ----
    #pragma unroll
    for (int q = 0; q < 4; q++) {
        int k = lcol + q * 4;
        float4 v = make_float4(0.f, 0.f, 0.f, 0.f);
        if (rv && k < Ksrc) v = *(const float4*)(Arow + q * 4);
        ar[q*4+0] = v.x; ar[q*4+1] = v.y; ar[q*4+2] = v.z; ar[q*4+3] = v.w;
    }
    cpa16(bdst_h,     Bh);
    cpa16(bdst_h + 16, Bh + 8);
    cpa16(bdst_l,     Bl);
    cpa16(bdst_l + 16, Bl + 8);
    cpa_commit();
    // convert A0 -> stage 0
    {
        __nv_bfloat16* sAhi = smp;
        __nv_bfloat16* sAlo = smp + ARR;
        #pragma unroll
        for (int q = 0; q < 4; q++) {
            float x0 = ar[q*4+0], x1 = ar[q*4+1], x2 = ar[q*4+2], x3 = ar[q*4+3];
            __nv_bfloat162 hxy, hzw, lxy, lzw;
            hxy.x = __float2bfloat16(x0); hxy.y = __float2bfloat16(x1);
            hzw.x = __float2bfloat16(x2); hzw.y = __float2bfloat16(x3);
            lxy.x = __float2bfloat16(x0 - __bfloat162float(hxy.x));
            lxy.y = __float2bfloat16(x1 - __bfloat162float(hxy.y));
            lzw.x = __float2bfloat16(x2 - __bfloat162float(hzw.x));
            lzw.y = __float2bfloat16(x3 - __bfloat162float(hzw.y));
            int o = lodst + q * 4;
            *(__nv_bfloat162*)&sAhi[o]     = hxy;
            *(__nv_bfloat162*)&sAhi[o + 2] = hzw;
            *(__nv_bfloat162*)&sAlo[o]     = lxy;
            *(__nv_bfloat162*)&sAlo[o + 2] = lzw;
        }
    }

    for (int ch = 0; ch < 8; ch++) {
        const int cur = ch & 1, nxt = cur ^ 1;
        // ---- prefetch chunk ch+1 ----
        if (ch < 7) {
            const int kn = (ch + 1) * 32;
            #pragma unroll
            for (int q = 0; q < 4; q++) {
                int k = kn + lcol + q * 4;
                float4 v = make_float4(0.f, 0.f, 0.f, 0.f);
                if (rv && k < Ksrc) v = *(const float4*)(Arow + kn + q * 4);
                ar[q*4+0] = v.x; ar[q*4+1] = v.y; ar[q*4+2] = v.z; ar[q*4+3] = v.w;
            }
            const uint32_t sb = (uint32_t)(nxt * STG) * 2;
            cpa16(bdst_h + sb,      Bh + kn);
            cpa16(bdst_h + sb + 16, Bh + kn + 8);
            cpa16(bdst_l + sb,      Bl + kn);
            cpa16(bdst_l + sb + 16, Bl + kn + 8);
            cpa_commit();
            asm volatile("cp.async.wait_group 1;" ::: "memory");
        } else {
            asm volatile("cp.async.wait_group 0;" ::: "memory");
        }
        __syncthreads();

        // ---- compute chunk ch from stage cur ----
        const uint32_t base = u0 + (uint32_t)(cur * STG) * 2;
        const uint32_t uAhi = base, uAlo = base + ARR * 2;
        const uint32_t uBhi = base + 2 * ARR * 2, uBlo = base + 3 * ARR * 2;
        #pragma unroll
        for (int kh = 0; kh < 2; kh++) {
            const int kb = kh * 16;
            uint32_t ah[2][4], al[2][4];
            #pragma unroll
            for (int mt = 0; mt < 2; mt++) {
                uint32_t off = (uint32_t)(((wm + mt * 16 + aro) * LDS + kb + ako) * 2);
                ldmx4(ah[mt], uAhi + off);
                ldmx4(al[mt], uAlo + off);
            }
            #pragma unroll
            for (int ng = 0; ng < 4; ng++) {
                uint32_t bh[4], bl[4];
                uint32_t off = (uint32_t)(((wn + ng * 16 + bro) * LDS + kb + bko) * 2);
                ldmx4(bh, uBhi + off);
                ldmx4(bl, uBlo + off);
                #pragma unroll
                for (int mt = 0; mt < 2; mt++) {
                    mma16816(c[mt][2*ng],   ah[mt], bh[0], bh[1]);
                    mma16816(c[mt][2*ng+1], ah[mt], bh[2], bh[3]);
                    mma16816(c[mt][2*ng],   ah[mt], bl[0], bl[1]);
                    mma16816(c[mt][2*ng+1], ah[mt], bl[2], bl[3]);
                    mma16816(c[mt][2*ng],   al[mt], bh[0], bh[1]);
                    mma16816(c[mt][2*ng+1], al[mt], bh[2], bh[3]);
                }
            }
        }

        // ---- convert A(ch+1) regs -> stage nxt ----
        if (ch < 7) {
            __nv_bfloat16* sAhi = smp + nxt * STG;
            __nv_bfloat16* sAlo = smp + nxt * STG + ARR;
            #pragma unroll
            for (int q = 0; q < 4; q++) {
                float x0 = ar[q*4+0], x1 = ar[q*4+1], x2 = ar[q*4+2], x3 = ar[q*4+3];
                __nv_bfloat162 hxy, hzw, lxy, lzw;
                hxy.x = __float2bfloat16(x0); hxy.y = __float2bfloat16(x1);
                hzw.x = __float2bfloat16(x2); hzw.y = __float2bfloat16(x3);
                lxy.x = __float2bfloat16(x0 - __bfloat162float(hxy.x));
                lxy.y = __float2bfloat16(x1 - __bfloat162float(hxy.y));
                lzw.x = __float2bfloat16(x2 - __bfloat162float(hzw.x));
                lzw.y = __float2bfloat16(x3 - __bfloat162float(hzw.y));
                int o = lodst + q * 4;
                *(__nv_bfloat162*)&sAhi[o]     = hxy;
                *(__nv_bfloat162*)&sAhi[o + 2] = hzw;
                *(__nv_bfloat162*)&sAlo[o]     = lxy;
                *(__nv_bfloat162*)&sAlo[o + 2] = lzw;
            }
        }
    }

    // ---- epilogue ----
    #pragma unroll
    for (int mt = 0; mt < 2; mt++) {
        int row = bm + wm + mt * 16 + (lane >> 2);
        #pragma unroll
        for (int nidx = 0; nidx < 8; nidx++) {
            int col = bn + wn + nidx * 8 + (lane & 3) * 2;
            float b0 = 0.f, b1 = 0.f;
            if (bias) { b0 = bias[col]; b1 = bias[col + 1]; }
            if (row < M) {
                float2 v = make_float2(c[mt][nidx][0] + b0, c[mt][nidx][1] + b1);
                *(float2*)(C + (size_t)row * N + col) = v;
            }
            if (row + 8 < M) {
                float2 v = make_float2(c[mt][nidx][2] + b0, c[mt][nidx][3] + b1);
                *(float2*)(C + (size_t)(row + 8) * N + col) = v;
            }
        }
    }
}

// ---------------- zero -------------------------------------------------------
__global__ void zero_kernel(float4* __restrict__ p, int n4) {
    int t = blockIdx.x * blockDim.x + threadIdx.x;
    if (t < n4) p[t] = make_float4(0.f, 0.f, 0.f, 0.f);
}

// ---------------- edge scatter: agg[dst] += m[src] ---------------------------
__global__ void scatter_kernel(const float* __restrict__ m,
                               const int* __restrict__ src,
                               const int* __restrict__ dst,
                               float* __restrict__ agg)
{
    long long t = (long long)blockIdx.x * blockDim.x + threadIdx.x;
    int e = (int)(t >> 6);
    if (e >= NE) return;
    int c = ((int)t & 63) << 2;
    int s = __ldg(src + e);
    int d = __ldg(dst + e);
    float4 v = *(const float4*)(m + (size_t)s * HH + c);
    float* p = agg + (size_t)d * HH + c;
    asm volatile("red.global.add.v4.f32 [%0], {%1,%2,%3,%4};"
                 :: "l"(p), "f"(v.x), "f"(v.y), "f"(v.z), "f"(v.w) : "memory");
}

// ---------------- GRU elementwise -------------------------------------------
__device__ __forceinline__ float gru1(float ir, float hr, float iz, float hz,
                                      float in_, float hn_, float h)
{
    float r  = 1.f / (1.f + __expf(-(ir + hr)));
    float z  = 1.f / (1.f + __expf(-(iz + hz)));
    float nn = tanhf(in_ + r * hn_);
    return (1.f - z) * nn + z * h;
}

__global__ void gru_kernel(const float* __restrict__ gi, const float* __restrict__ gh,
                           const float* __restrict__ h, float* __restrict__ hn)
{
    int t = blockIdx.x * blockDim.x + threadIdx.x;
    if (t >= NN * (HH/4)) return;
    int i = t >> 6;
    int c = (t & 63) << 2;
    size_t b3 = (size_t)i * H3 + c;
    size_t b1 = (size_t)i * HH + c;
    float4 ir  = *(const float4*)(gi + b3);
    float4 hr  = *(const float4*)(gh + b3);
    float4 iz  = *(const float4*)(gi + b3 + HH);
    float4 hz  = *(const float4*)(gh + b3 + HH);
    float4 in_ = *(const float4*)(gi + b3 + 2*HH);
    float4 hn_ = *(const float4*)(gh + b3 + 2*HH);
    float4 hv  = *(const float4*)(h + b1);
    float4 o;
    o.x = gru1(ir.x, hr.x, iz.x, hz.x, in_.x, hn_.x, hv.x);
    o.y = gru1(ir.y, hr.y, iz.y, hz.y, in_.y, hn_.y, hv.y);
    o.z = gru1(ir.z, hr.z, iz.z, hz.z, in_.z, hn_.z, hv.z);
    o.w = gru1(ir.w, hr.w, iz.w, hz.w, in_.w, hn_.w, hv.w);
    *(float4*)(hn + b1) = o;
}

// ---------------- head: relu(h) @ W_lin^T + b, log_softmax -------------------
__global__ void head_kernel(const float* __restrict__ h,
                            const float* __restrict__ W_lin,
                            const float* __restrict__ b_lin,
                            float* __restrict__ out)
{
    int gw = (blockIdx.x * blockDim.x + threadIdx.x) >> 5;
    int lane = threadIdx.x & 31;
    if (gw >= NN) return;
    const float* hr = h + (size_t)gw * HH;
    float a0 = 0.f, a1 = 0.f;
    #pragma unroll
    for (int k = lane; k < HH; k += 32) {
        float v = hr[k];
        v = v > 0.f ? v : 0.f;
        a0 += v * __ldg(W_lin + k);
        a1 += v * __ldg(W_lin + HH + k);
    }
    #pragma unroll
    for (int off = 16; off; off >>= 1) {
        a0 += __shfl_xor_sync(0xffffffffu, a0, off);
        a1 += __shfl_xor_sync(0xffffffffu, a1, off);
    }
    if (lane == 0) {
        float o0 = a0 + b_lin[0];
        float o1 = a1 + b_lin[1];
        float mx = fmaxf(o0, o1);
        float lse = mx + logf(expf(o0 - mx) + expf(o1 - mx));
        out[2*gw]     = o0 - lse;
        out[2*gw + 1] = o1 - lse;
    }
}

// ---------------- launch -----------------------------------------------------
extern "C" void kernel_launch(void* const* d_in, const int* in_sizes, int n_in,
                              void* d_out, int out_size)
{
    const float* x        = (const float*)d_in[0];
    const int*   edge     = (const int*)  d_in[1];
    const float* W_reduce = (const float*)d_in[3];
    const float* b_reduce = (const float*)d_in[4];
    const float* W_ggc    = (const float*)d_in[5];
    const float* W_ih     = (const float*)d_in[6];
    const float* W_hh     = (const float*)d_in[7];
    const float* b_ih     = (const float*)d_in[8];
    const float* b_hh     = (const float*)d_in[9];
    const float* W_lin    = (const float*)d_in[10];
    const float* b_lin    = (const float*)d_in[11];
    float* out = (float*)d_out;

    const int* src = edge;
    const int* dst = edge + NE;

    float *h0, *h1, *mbuf, *agg, *gi, *gh;
    cudaGetSymbolAddress((void**)&h0,   g_h0);
    cudaGetSymbolAddress((void**)&h1,   g_h1);
    cudaGetSymbolAddress((void**)&mbuf, g_m);
    cudaGetSymbolAddress((void**)&agg,  g_agg);
    cudaGetSymbolAddress((void**)&gi,   g_gi);
    cudaGetSymbolAddress((void**)&gh,   g_gh);

    __nv_bfloat16 *wred_h, *wred_l, *wggc_h, *wggc_l, *wih_h, *wih_l, *whh_h, *whh_l;
    cudaGetSymbolAddress((void**)&wred_h, g_wred_hi);
    cudaGetSymbolAddress((void**)&wred_l, g_wred_lo);
    cudaGetSymbolAddress((void**)&wggc_h, g_wggc_hi);
    cudaGetSymbolAddress((void**)&wggc_l, g_wggc_lo);
    cudaGetSymbolAddress((void**)&wih_h,  g_wih_hi);
    cudaGetSymbolAddress((void**)&wih_l,  g_wih_lo);
    cudaGetSymbolAddress((void**)&whh_h,  g_whh_hi);
    cudaGetSymbolAddress((void**)&whh_l,  g_whh_lo);

    cudaFuncSetAttribute(mma_gemm, cudaFuncAttributeMaxDynamicSharedMemorySize, SMEM_BYTES);

    // weight conversions (per launch, deterministic)
    conv_w<<<(HH*KP + 255)/256, 256>>>(W_reduce, wred_h, wred_l, HH, 200);
    conv_w<<<(H3*KP + 255)/256, 256>>>(W_ih, wih_h, wih_l, H3, KP);
    conv_w<<<(H3*KP + 255)/256, 256>>>(W_hh, whh_h, whh_l, H3, KP);
    conv_wggcT<<<(8*HH*KP + 255)/256, 256>>>(W_ggc, wggc_h, wggc_l);

    const int mtiles = (NN + 127) / 128;   // 391

    // h = x @ W_reduce^T + b_reduce
    mma_gemm<<<dim3(HH/128, mtiles), 256, SMEM_BYTES>>>(x, wred_h, wred_l, b_reduce, h0, NN, HH, 200);

    float* hc = h0;
    float* hn = h1;
    for (int s = 0; s < 8; s++) {
        mma_gemm<<<dim3(HH/128, mtiles), 256, SMEM_BYTES>>>(hc, wggc_h + (size_t)s*HH*KP,
                                                            wggc_l + (size_t)s*HH*KP,
                                                            nullptr, mbuf, NN, HH, KP);
        zero_kernel<<<(NN*HH/4 + 255)/256, 256>>>((float4*)agg, NN*HH/4);
        scatter_kernel<<<((long long)NE*64 + 255)/256, 256>>>(mbuf, src, dst, agg);
        mma_gemm<<<dim3(H3/128, mtiles), 256, SMEM_BYTES>>>(agg, wih_h, wih_l, b_ih, gi, NN, H3, KP);
        mma_gemm<<<dim3(H3/128, mtiles), 256, SMEM_BYTES>>>(hc,  whh_h, whh_l, b_hh, gh, NN, H3, KP);
        gru_kernel<<<(NN*(HH/4) + 255)/256, 256>>>(gi, gh, hc, hn);
        float* t = hc; hc = hn; hn = t;
    }

    head_kernel<<<(NN*32 + 255)/256, 256>>>(hc, W_lin, b_lin, out);
}

// round 7
// speedup vs baseline: 3.5639x; 1.4706x over previous
#include <cuda_runtime.h>
#include <cuda_fp16.h>
#include <math.h>
#include <stdint.h>

#define NN 50000
#define HH 256
#define NE 300000
#define H3 (3*HH)
#define KP 256   // padded K for all GEMMs

// ---------------- scratch (static device globals; allocation-free) ----------
__device__ float g_h0[NN*HH];
__device__ float g_h1[NN*HH];
__device__ float g_m [NN*HH];
__device__ float g_agg[NN*HH];
__device__ float g_gi[(size_t)NN*H3];
__device__ float g_gh[(size_t)NN*H3];

// fp16 weights, [N, 256] K-major row-major
__device__ __half g_wred[HH*KP];
__device__ __half g_wggc[8*HH*KP];
__device__ __half g_wih[H3*KP];
__device__ __half g_whh[H3*KP];

// ---------------- weight conversion ----------------------------------------
__global__ void conv_w(const float* __restrict__ W, __half* __restrict__ o,
                       int Nrows, int Ksrc)
{
    int t = blockIdx.x * blockDim.x + threadIdx.x;
    if (t >= Nrows * KP) return;
    int n = t >> 8, k = t & 255;
    float v = (k < Ksrc) ? W[(size_t)n * Ksrc + k] : 0.f;
    o[t] = __float2half_rn(v);
}

// W_ggc [8,K,N] -> transposed [8,N,K]
__global__ void conv_wggcT(const float* __restrict__ W, __half* __restrict__ o)
{
    int t = blockIdx.x * blockDim.x + threadIdx.x;
    if (t >= 8 * HH * KP) return;
    int s = t >> 16, n = (t >> 8) & 255, k = t & 255;
    o[t] = __float2half_rn(W[((size_t)s << 16) + (size_t)k * HH + n]);
}

// ---------------- helpers ----------------------------------------------------
__device__ __forceinline__ uint32_t smem_u32(const void* p) {
    uint32_t a;
    asm("{ .reg .u64 t; cvta.to.shared.u64 t, %1; cvt.u32.u64 %0, t; }" : "=r"(a) : "l"(p));
    return a;
}

__device__ __forceinline__ void ldmx4(uint32_t* r, uint32_t addr) {
    asm volatile("ldmatrix.sync.aligned.m8n8.x4.shared.b16 {%0,%1,%2,%3}, [%4];"
                 : "=r"(r[0]), "=r"(r[1]), "=r"(r[2]), "=r"(r[3]) : "r"(addr));
}

__device__ __forceinline__ void mma16816(float* d, const uint32_t* a, uint32_t b0, uint32_t b1) {
    asm volatile(
        "mma.sync.aligned.m16n8k16.row.col.f32.f16.f16.f32 "
        "{%0,%1,%2,%3}, {%4,%5,%6,%7}, {%8,%9}, {%0,%1,%2,%3};"
        : "+f"(d[0]), "+f"(d[1]), "+f"(d[2]), "+f"(d[3])
        : "r"(a[0]), "r"(a[1]), "r"(a[2]), "r"(a[3]), "r"(b0), "r"(b1));
}

__device__ __forceinline__ void cpa16(uint32_t dst, const void* src) {
    asm volatile("cp.async.ca.shared.global [%0], [%1], 16;" :: "r"(dst), "l"(src) : "memory");
}
__device__ __forceinline__ void cpa_commit() {
    asm volatile("cp.async.commit_group;" ::: "memory");
}

// ---------------- GEMM: C[M,N] = A(fp32)[M,Ksrc<=256] @ B(fp16)[N,256]^T + bias
// block 128x128, 8 warps (4 in M x 2 in N), warp tile 32x64, K-chunk 32.
// Two-stage pipeline: B via cp.async, A via register prefetch + fp16 convert.
#define LDS 40                      // smem row stride in fp16 (32 data + 8 pad)
#define ARR (128*LDS)               // elems per array
#define STG (2*ARR)                 // elems per stage (A, B)
#define SMEM_BYTES (2*STG*2)        // 40960 B

__global__ __launch_bounds__(256)
void mma_gemm(const float* __restrict__ A,
              const __half* __restrict__ B,
              const float* __restrict__ bias,
              float* __restrict__ C, int M, int N, int Ksrc)
{
    extern __shared__ __half smp[];

    const int tid = threadIdx.x;
    const int lane = tid & 31, wid = tid >> 5;
    const int bm = blockIdx.y * 128, bn = blockIdx.x * 128;
    const int wm = (wid & 3) * 32, wn = (wid >> 2) * 64;

    float c[2][8][4];
    #pragma unroll
    for (int i = 0; i < 2; i++)
        #pragma unroll
        for (int j = 0; j < 8; j++)
            #pragma unroll
            for (int q = 0; q < 4; q++) c[i][j][q] = 0.f;

    // loader mapping: row = tid>>1 (0..127), 16 cols at (tid&1)*16
    const int lrow = tid >> 1;
    const int lcol = (tid & 1) * 16;
    const bool rv = (bm + lrow) < M;
    const float* Arow = A + (size_t)(bm + lrow) * Ksrc + lcol;
    const __half* Brow = B + (size_t)(bn + lrow) * KP + lcol;

    const uint32_t u0 = smem_u32(smp);
    const int lodst = lrow * LDS + lcol;                        // elem offset within array
    const uint32_t bdst = u0 + (uint32_t)(ARR + lodst) * 2;     // B byte offset in stage 0

    // ldmatrix per-thread row/col offsets
    const int aro = (lane & 7) + ((lane >> 3) & 1) * 8;
    const int ako = ((lane >> 4) & 1) * 8;
    const int bro = (lane & 7) + ((lane >> 4) & 1) * 8;
    const int bko = ((lane >> 3) & 1) * 8;

    float ar[16];

    // ---- prologue: chunk 0 ----
    #pragma unroll
    for (int q = 0; q < 4; q++) {
        int k = lcol + q * 4;
        float4 v = make_float4(0.f, 0.f, 0.f, 0.f);
        if (rv && k < Ksrc) v = *(const float4*)(Arow + q * 4);
        ar[q*4+0] = v.x; ar[q*4+1] = v.y; ar[q*4+2] = v.z; ar[q*4+3] = v.w;
    }
    cpa16(bdst,      Brow);
    cpa16(bdst + 16, Brow + 8);
    cpa_commit();
    {
        __half* sA = smp;
        #pragma unroll
        for (int q = 0; q < 4; q++) {
            __half2 p0 = __floats2half2_rn(ar[q*4+0], ar[q*4+1]);
            __half2 p1 = __floats2half2_rn(ar[q*4+2], ar[q*4+3]);
            int o = lodst + q * 4;
            *(__half2*)&sA[o]     = p0;
            *(__half2*)&sA[o + 2] = p1;
        }
    }

    for (int ch = 0; ch < 8; ch++) {
        const int cur = ch & 1, nxt = cur ^ 1;
        // ---- prefetch chunk ch+1 ----
        if (ch < 7) {
            const int kn = (ch + 1) * 32;
            #pragma unroll
            for (int q = 0; q < 4; q++) {
                int k = kn + lcol + q * 4;
                float4 v = make_float4(0.f, 0.f, 0.f, 0.f);
                if (rv && k < Ksrc) v = *(const float4*)(Arow + kn + q * 4);
                ar[q*4+0] = v.x; ar[q*4+1] = v.y; ar[q*4+2] = v.z; ar[q*4+3] = v.w;
            }
            const uint32_t sb = (uint32_t)(nxt * STG) * 2;
            cpa16(bdst + sb,      Brow + kn);
            cpa16(bdst + sb + 16, Brow + kn + 8);
            cpa_commit();
            asm volatile("cp.async.wait_group 1;" ::: "memory");
        } else {
            asm volatile("cp.async.wait_group 0;" ::: "memory");
        }
        __syncthreads();

        // ---- compute chunk ch from stage cur ----
        const uint32_t base = u0 + (uint32_t)(cur * STG) * 2;
        const uint32_t uA = base, uB = base + ARR * 2;
        #pragma unroll
        for (int kh = 0; kh < 2; kh++) {
            const int kb = kh * 16;
            uint32_t ah[2][4];
            #pragma unroll
            for (int mt = 0; mt < 2; mt++) {
                uint32_t off = (uint32_t)(((wm + mt * 16 + aro) * LDS + kb + ako) * 2);
                ldmx4(ah[mt], uA + off);
            }
            #pragma unroll
            for (int ng = 0; ng < 4; ng++) {
                uint32_t bh[4];
                uint32_t off = (uint32_t)(((wn + ng * 16 + bro) * LDS + kb + bko) * 2);
                ldmx4(bh, uB + off);
                #pragma unroll
                for (int mt = 0; mt < 2; mt++) {
                    mma16816(c[mt][2*ng],   ah[mt], bh[0], bh[1]);
                    mma16816(c[mt][2*ng+1], ah[mt], bh[2], bh[3]);
                }
            }
        }

        // ---- convert A(ch+1) regs -> stage nxt ----
        if (ch < 7) {
            __half* sA = smp + nxt * STG;
            #pragma unroll
            for (int q = 0; q < 4; q++) {
                __half2 p0 = __floats2half2_rn(ar[q*4+0], ar[q*4+1]);
                __half2 p1 = __floats2half2_rn(ar[q*4+2], ar[q*4+3]);
                int o = lodst + q * 4;
                *(__half2*)&sA[o]     = p0;
                *(__half2*)&sA[o + 2] = p1;
            }
        }
    }

    // ---- epilogue ----
    #pragma unroll
    for (int mt = 0; mt < 2; mt++) {
        int row = bm + wm + mt * 16 + (lane >> 2);
        #pragma unroll
        for (int nidx = 0; nidx < 8; nidx++) {
            int col = bn + wn + nidx * 8 + (lane & 3) * 2;
            float b0 = 0.f, b1 = 0.f;
            if (bias) { b0 = bias[col]; b1 = bias[col + 1]; }
            if (row < M) {
                float2 v = make_float2(c[mt][nidx][0] + b0, c[mt][nidx][1] + b1);
                *(float2*)(C + (size_t)row * N + col) = v;
            }
            if (row + 8 < M) {
                float2 v = make_float2(c[mt][nidx][2] + b0, c[mt][nidx][3] + b1);
                *(float2*)(C + (size_t)(row + 8) * N + col) = v;
            }
        }
    }
}

// ---------------- zero -------------------------------------------------------
__global__ void zero_kernel(float4* __restrict__ p, int n4) {
    int t = blockIdx.x * blockDim.x + threadIdx.x;
    if (t < n4) p[t] = make_float4(0.f, 0.f, 0.f, 0.f);
}

// ---------------- edge scatter: agg[dst] += m[src] ---------------------------
__global__ void scatter_kernel(const float* __restrict__ m,
                               const int* __restrict__ src,
                               const int* __restrict__ dst,
                               float* __restrict__ agg)
{
    long long t = (long long)blockIdx.x * blockDim.x + threadIdx.x;
    int e = (int)(t >> 6);
    if (e >= NE) return;
    int c = ((int)t & 63) << 2;
    int s = __ldg(src + e);
    int d = __ldg(dst + e);
    float4 v = *(const float4*)(m + (size_t)s * HH + c);
    float* p = agg + (size_t)d * HH + c;
    asm volatile("red.global.add.v4.f32 [%0], {%1,%2,%3,%4};"
                 :: "l"(p), "f"(v.x), "f"(v.y), "f"(v.z), "f"(v.w) : "memory");
}

// ---------------- GRU elementwise -------------------------------------------
__device__ __forceinline__ float gru1(float ir, float hr, float iz, float hz,
                                      float in_, float hn_, float h)
{
    float r  = 1.f / (1.f + __expf(-(ir + hr)));
    float z  = 1.f / (1.f + __expf(-(iz + hz)));
    float nn = tanhf(in_ + r * hn_);
    return (1.f - z) * nn + z * h;
}

__global__ void gru_kernel(const float* __restrict__ gi, const float* __restrict__ gh,
                           const float* __restrict__ h, float* __restrict__ hn)
{
    int t = blockIdx.x * blockDim.x + threadIdx.x;
    if (t >= NN * (HH/4)) return;
    int i = t >> 6;
    int c = (t & 63) << 2;
    size_t b3 = (size_t)i * H3 + c;
    size_t b1 = (size_t)i * HH + c;
    float4 ir  = *(const float4*)(gi + b3);
    float4 hr  = *(const float4*)(gh + b3);
    float4 iz  = *(const float4*)(gi + b3 + HH);
    float4 hz  = *(const float4*)(gh + b3 + HH);
    float4 in_ = *(const float4*)(gi + b3 + 2*HH);
    float4 hn_ = *(const float4*)(gh + b3 + 2*HH);
    float4 hv  = *(const float4*)(h + b1);
    float4 o;
    o.x = gru1(ir.x, hr.x, iz.x, hz.x, in_.x, hn_.x, hv.x);
    o.y = gru1(ir.y, hr.y, iz.y, hz.y, in_.y, hn_.y, hv.y);
    o.z = gru1(ir.z, hr.z, iz.z, hz.z, in_.z, hn_.z, hv.z);
    o.w = gru1(ir.w, hr.w, iz.w, hz.w, in_.w, hn_.w, hv.w);
    *(float4*)(hn + b1) = o;
}

// ---------------- head: relu(h) @ W_lin^T + b, log_softmax -------------------
__global__ void head_kernel(const float* __restrict__ h,
                            const float* __restrict__ W_lin,
                            const float* __restrict__ b_lin,
                            float* __restrict__ out)
{
    int gw = (blockIdx.x * blockDim.x + threadIdx.x) >> 5;
    int lane = threadIdx.x & 31;
    if (gw >= NN) return;
    const float* hr = h + (size_t)gw * HH;
    float a0 = 0.f, a1 = 0.f;
    #pragma unroll
    for (int k = lane; k < HH; k += 32) {
        float v = hr[k];
        v = v > 0.f ? v : 0.f;
        a0 += v * __ldg(W_lin + k);
        a1 += v * __ldg(W_lin + HH + k);
    }
    #pragma unroll
    for (int off = 16; off; off >>= 1) {
        a0 += __shfl_xor_sync(0xffffffffu, a0, off);
        a1 += __shfl_xor_sync(0xffffffffu, a1, off);
    }
    if (lane == 0) {
        float o0 = a0 + b_lin[0];
        float o1 = a1 + b_lin[1];
        float mx = fmaxf(o0, o1);
        float lse = mx + logf(expf(o0 - mx) + expf(o1 - mx));
        out[2*gw]     = o0 - lse;
        out[2*gw + 1] = o1 - lse;
    }
}

// ---------------- launch -----------------------------------------------------
extern "C" void kernel_launch(void* const* d_in, const int* in_sizes, int n_in,
                              void* d_out, int out_size)
{
    const float* x        = (const float*)d_in[0];
    const int*   edge     = (const int*)  d_in[1];
    const float* W_reduce = (const float*)d_in[3];
    const float* b_reduce = (const float*)d_in[4];
    const float* W_ggc    = (const float*)d_in[5];
    const float* W_ih     = (const float*)d_in[6];
    const float* W_hh     = (const float*)d_in[7];
    const float* b_ih     = (const float*)d_in[8];
    const float* b_hh     = (const float*)d_in[9];
    const float* W_lin    = (const float*)d_in[10];
    const float* b_lin    = (const float*)d_in[11];
    float* out = (float*)d_out;

    const int* src = edge;
    const int* dst = edge + NE;

    float *h0, *h1, *mbuf, *agg, *gi, *gh;
    cudaGetSymbolAddress((void**)&h0,   g_h0);
    cudaGetSymbolAddress((void**)&h1,   g_h1);
    cudaGetSymbolAddress((void**)&mbuf, g_m);
    cudaGetSymbolAddress((void**)&agg,  g_agg);
    cudaGetSymbolAddress((void**)&gi,   g_gi);
    cudaGetSymbolAddress((void**)&gh,   g_gh);

    __half *wred, *wggc, *wih, *whh;
    cudaGetSymbolAddress((void**)&wred, g_wred);
    cudaGetSymbolAddress((void**)&wggc, g_wggc);
    cudaGetSymbolAddress((void**)&wih,  g_wih);
    cudaGetSymbolAddress((void**)&whh,  g_whh);

    cudaFuncSetAttribute(mma_gemm, cudaFuncAttributeMaxDynamicSharedMemorySize, SMEM_BYTES);

    // weight conversions (per launch, deterministic)
    conv_w<<<(HH*KP + 255)/256, 256>>>(W_reduce, wred, HH, 200);
    conv_w<<<(H3*KP + 255)/256, 256>>>(W_ih, wih, H3, KP);
    conv_w<<<(H3*KP + 255)/256, 256>>>(W_hh, whh, H3, KP);
    conv_wggcT<<<(8*HH*KP + 255)/256, 256>>>(W_ggc, wggc);

    const int mtiles = (NN + 127) / 128;   // 391

    // h = x @ W_reduce^T + b_reduce
    mma_gemm<<<dim3(HH/128, mtiles), 256, SMEM_BYTES>>>(x, wred, b_reduce, h0, NN, HH, 200);

    float* hc = h0;
    float* hn = h1;
    for (int s = 0; s < 8; s++) {
        mma_gemm<<<dim3(HH/128, mtiles), 256, SMEM_BYTES>>>(hc, wggc + (size_t)s*HH*KP,
                                                            nullptr, mbuf, NN, HH, KP);
        zero_kernel<<<(NN*HH/4 + 255)/256, 256>>>((float4*)agg, NN*HH/4);
        scatter_kernel<<<((long long)NE*64 + 255)/256, 256>>>(mbuf, src, dst, agg);
        mma_gemm<<<dim3(H3/128, mtiles), 256, SMEM_BYTES>>>(agg, wih, b_ih, gi, NN, H3, KP);
        mma_gemm<<<dim3(H3/128, mtiles), 256, SMEM_BYTES>>>(hc,  whh, b_hh, gh, NN, H3, KP);
        gru_kernel<<<(NN*(HH/4) + 255)/256, 256>>>(gi, gh, hc, hn);
        float* t = hc; hc = hn; hn = t;
    }

    head_kernel<<<(NN*32 + 255)/256, 256>>>(hc, W_lin, b_lin, out);
}

// round 8
// speedup vs baseline: 3.8196x; 1.0717x over previous
#include <cuda_runtime.h>
#include <cuda_fp16.h>
#include <math.h>
#include <stdint.h>

#define NN 50000
#define HH 256
#define NE 300000
#define H3 (3*HH)
#define KP 256
#define NPAD (NN + 128)

// ---------------- scratch ----------------------------------------------------
__device__ float g_h0[NN*HH];
__device__ float g_h1[NN*HH];
__device__ float g_m [NN*HH];
__device__ float g_agg[NN*HH];
__device__ __half g_h16a[(size_t)NPAD*HH];
__device__ __half g_h16b[(size_t)NPAD*HH];
__device__ __half g_agg16[(size_t)NPAD*HH];

// fp16 weights, [rows, 256] K-major
__device__ __half g_wred[HH*KP];
__device__ __half g_wggc[8*HH*KP];
__device__ __half g_wih[H3*KP];
__device__ __half g_whh[H3*KP];

// ---------------- weight conversion ------------------------------------------
__global__ void conv_w(const float* __restrict__ W, __half* __restrict__ o,
                       int Nrows, int Ksrc)
{
    int t = blockIdx.x * blockDim.x + threadIdx.x;
    if (t >= Nrows * KP) return;
    int n = t >> 8, k = t & 255;
    float v = (k < Ksrc) ? W[(size_t)n * Ksrc + k] : 0.f;
    o[t] = __float2half_rn(v);
}

__global__ void conv_wggcT(const float* __restrict__ W, __half* __restrict__ o)
{
    int t = blockIdx.x * blockDim.x + threadIdx.x;
    if (t >= 8 * HH * KP) return;
    int s = t >> 16, n = (t >> 8) & 255, k = t & 255;
    o[t] = __float2half_rn(W[((size_t)s << 16) + (size_t)k * HH + n]);
}

// fp32 -> fp16 shadow copy
__global__ void cvt16(const float* __restrict__ in, __half* __restrict__ o, int n8) {
    int t = blockIdx.x * blockDim.x + threadIdx.x;
    if (t >= n8) return;
    float4 a = *(const float4*)(in + t * 8);
    float4 b = *(const float4*)(in + t * 8 + 4);
    __half2 h[4];
    h[0] = __floats2half2_rn(a.x, a.y);
    h[1] = __floats2half2_rn(a.z, a.w);
    h[2] = __floats2half2_rn(b.x, b.y);
    h[3] = __floats2half2_rn(b.z, b.w);
    *(uint4*)(o + t * 8) = *(uint4*)h;
}

// ---------------- asm helpers ------------------------------------------------
__device__ __forceinline__ uint32_t smem_u32(const void* p) {
    uint32_t a;
    asm("{ .reg .u64 t; cvta.to.shared.u64 t, %1; cvt.u32.u64 %0, t; }" : "=r"(a) : "l"(p));
    return a;
}
__device__ __forceinline__ void ldmx4(uint32_t* r, uint32_t addr) {
    asm volatile("ldmatrix.sync.aligned.m8n8.x4.shared.b16 {%0,%1,%2,%3}, [%4];"
                 : "=r"(r[0]), "=r"(r[1]), "=r"(r[2]), "=r"(r[3]) : "r"(addr));
}
__device__ __forceinline__ void mma16816(float* d, const uint32_t* a, uint32_t b0, uint32_t b1) {
    asm volatile(
        "mma.sync.aligned.m16n8k16.row.col.f32.f16.f16.f32 "
        "{%0,%1,%2,%3}, {%4,%5,%6,%7}, {%8,%9}, {%0,%1,%2,%3};"
        : "+f"(d[0]), "+f"(d[1]), "+f"(d[2]), "+f"(d[3])
        : "r"(a[0]), "r"(a[1]), "r"(a[2]), "r"(a[3]), "r"(b0), "r"(b1));
}
__device__ __forceinline__ void cpa16(uint32_t dst, const void* src) {
    asm volatile("cp.async.ca.shared.global [%0], [%1], 16;" :: "r"(dst), "l"(src) : "memory");
}
__device__ __forceinline__ void cpa_commit() {
    asm volatile("cp.async.commit_group;" ::: "memory");
}
__device__ __forceinline__ void cpa_wait0() {
    asm volatile("cp.async.wait_group 0;" ::: "memory");
}

#define LDSW 40

// ============ GEMM A=fp32 (reduce only): C = A @ B^T + bias ==================
#define ARR (128*LDSW)
#define STG (2*ARR)
#define SMEM_G (2*STG*2)

__global__ __launch_bounds__(256)
void mma_gemm(const float* __restrict__ A, const __half* __restrict__ B,
              const float* __restrict__ bias, float* __restrict__ C,
              int M, int N, int Ksrc)
{
    extern __shared__ __half smp[];
    const int tid = threadIdx.x, lane = tid & 31, wid = tid >> 5;
    const int bm = blockIdx.y * 128, bn = blockIdx.x * 128;
    const int wm = (wid & 3) * 32, wn = (wid >> 2) * 64;

    float c[2][8][4];
    #pragma unroll
    for (int i = 0; i < 2; i++)
        #pragma unroll
        for (int j = 0; j < 8; j++)
            #pragma unroll
            for (int q = 0; q < 4; q++) c[i][j][q] = 0.f;

    const int lrow = tid >> 1, lcol = (tid & 1) * 16;
    const bool rv = (bm + lrow) < M;
    const float* Arow = A + (size_t)(bm + lrow) * Ksrc + lcol;
    const __half* Brow = B + (size_t)(bn + lrow) * KP + lcol;

    const uint32_t u0 = smem_u32(smp);
    const int lodst = lrow * LDSW + lcol;
    const uint32_t bdst = u0 + (uint32_t)(ARR + lodst) * 2;

    const int aro = (lane & 7) + ((lane >> 3) & 1) * 8;
    const int ako = ((lane >> 4) & 1) * 8;
    const int bro = (lane & 7) + ((lane >> 4) & 1) * 8;
    const int bko = ((lane >> 3) & 1) * 8;

    // prologue: stage 0 (A direct convert, B cp.async)
    {
        #pragma unroll
        for (int q = 0; q < 4; q++) {
            int k = lcol + q * 4;
            float4 v = make_float4(0.f,0.f,0.f,0.f);
            if (rv && k < Ksrc) v = *(const float4*)(Arow + q * 4);
            __half2 p0 = __floats2half2_rn(v.x, v.y);
            __half2 p1 = __floats2half2_rn(v.z, v.w);
            int o = lodst + q * 4;
            *(__half2*)&smp[o] = p0; *(__half2*)&smp[o+2] = p1;
        }
        cpa16(bdst, Brow); cpa16(bdst + 16, Brow + 8);
        cpa_commit();
    }

    for (int ch = 0; ch < 8; ch++) {
        const int cur = ch & 1, nxt = cur ^ 1;
        cpa_wait0();
        __syncthreads();
        // prefetch B for ch+1 (A handled post-compute via regs)
        float ar[16];
        if (ch < 7) {
            const int kn = (ch + 1) * 32;
            #pragma unroll
            for (int q = 0; q < 4; q++) {
                int k = kn + lcol + q * 4;
                float4 v = make_float4(0.f,0.f,0.f,0.f);
                if (rv && k < Ksrc) v = *(const float4*)(Arow + kn + q * 4);
                ar[q*4+0]=v.x; ar[q*4+1]=v.y; ar[q*4+2]=v.z; ar[q*4+3]=v.w;
            }
            const uint32_t sb = (uint32_t)(nxt * STG) * 2;
            cpa16(bdst + sb, Brow + kn); cpa16(bdst + sb + 16, Brow + kn + 8);
            cpa_commit();
        }
        // compute cur
        const uint32_t base = u0 + (uint32_t)(cur * STG) * 2;
        const uint32_t uA = base, uB = base + ARR * 2;
        #pragma unroll
        for (int kh = 0; kh < 2; kh++) {
            const int kb = kh * 16;
            uint32_t ah[2][4];
            #pragma unroll
            for (int mt = 0; mt < 2; mt++)
                ldmx4(ah[mt], uA + (uint32_t)(((wm + mt*16 + aro) * LDSW + kb + ako) * 2));
            #pragma unroll
            for (int ng = 0; ng < 4; ng++) {
                uint32_t bh[4];
                ldmx4(bh, uB + (uint32_t)(((wn + ng*16 + bro) * LDSW + kb + bko) * 2));
                #pragma unroll
                for (int mt = 0; mt < 2; mt++) {
                    mma16816(c[mt][2*ng],   ah[mt], bh[0], bh[1]);
                    mma16816(c[mt][2*ng+1], ah[mt], bh[2], bh[3]);
                }
            }
        }
        // convert A(ch+1) -> stage nxt
        if (ch < 7) {
            __half* sA = smp + nxt * STG;
            #pragma unroll
            for (int q = 0; q < 4; q++) {
                __half2 p0 = __floats2half2_rn(ar[q*4+0], ar[q*4+1]);
                __half2 p1 = __floats2half2_rn(ar[q*4+2], ar[q*4+3]);
                int o = lodst + q * 4;
                *(__half2*)&sA[o] = p0; *(__half2*)&sA[o+2] = p1;
            }
        }
    }

    #pragma unroll
    for (int mt = 0; mt < 2; mt++) {
        int row = bm + wm + mt * 16 + (lane >> 2);
        #pragma unroll
        for (int nidx = 0; nidx < 8; nidx++) {
            int col = bn + wn + nidx * 8 + (lane & 3) * 2;
            float b0 = 0.f, b1 = 0.f;
            if (bias) { b0 = bias[col]; b1 = bias[col + 1]; }
            if (row < M)
                *(float2*)(C + (size_t)row * N + col) =
                    make_float2(c[mt][nidx][0] + b0, c[mt][nidx][1] + b1);
            if (row + 8 < M)
                *(float2*)(C + (size_t)(row + 8) * N + col) =
                    make_float2(c[mt][nidx][2] + b0, c[mt][nidx][3] + b1);
        }
    }
}

// ============ GEMM A=fp16 (ggc): C = A @ B^T ================================
__global__ __launch_bounds__(256)
void mma_gemm16(const __half* __restrict__ A, const __half* __restrict__ B,
                float* __restrict__ C, int M, int N)
{
    extern __shared__ __half smp[];
    const int tid = threadIdx.x, lane = tid & 31, wid = tid >> 5;
    const int bm = blockIdx.y * 128, bn = blockIdx.x * 128;
    const int wm = (wid & 3) * 32, wn = (wid >> 2) * 64;

    float c[2][8][4];
    #pragma unroll
    for (int i = 0; i < 2; i++)
        #pragma unroll
        for (int j = 0; j < 8; j++)
            #pragma unroll
            for (int q = 0; q < 4; q++) c[i][j][q] = 0.f;

    const int lrow = tid >> 1, lcol = (tid & 1) * 16;
    const __half* Arow = A + (size_t)(bm + lrow) * KP + lcol;  // padded buffer
    const __half* Brow = B + (size_t)(bn + lrow) * KP + lcol;

    const uint32_t u0 = smem_u32(smp);
    const int lodst = lrow * LDSW + lcol;
    const uint32_t adst = u0 + (uint32_t)lodst * 2;
    const uint32_t bdst = u0 + (uint32_t)(ARR + lodst) * 2;

    const int aro = (lane & 7) + ((lane >> 3) & 1) * 8;
    const int ako = ((lane >> 4) & 1) * 8;
    const int bro = (lane & 7) + ((lane >> 4) & 1) * 8;
    const int bko = ((lane >> 3) & 1) * 8;

    cpa16(adst, Arow); cpa16(adst + 16, Arow + 8);
    cpa16(bdst, Brow); cpa16(bdst + 16, Brow + 8);
    cpa_commit();

    for (int ch = 0; ch < 8; ch++) {
        const int cur = ch & 1, nxt = cur ^ 1;
        cpa_wait0();
        __syncthreads();
        if (ch < 7) {
            const int kn = (ch + 1) * 32;
            const uint32_t sb = (uint32_t)(nxt * STG) * 2;
            cpa16(adst + sb, Arow + kn); cpa16(adst + sb + 16, Arow + kn + 8);
            cpa16(bdst + sb, Brow + kn); cpa16(bdst + sb + 16, Brow + kn + 8);
            cpa_commit();
        }
        const uint32_t base = u0 + (uint32_t)(cur * STG) * 2;
        const uint32_t uA = base, uB = base + ARR * 2;
        #pragma unroll
        for (int kh = 0; kh < 2; kh++) {
            const int kb = kh * 16;
            uint32_t ah[2][4];
            #pragma unroll
            for (int mt = 0; mt < 2; mt++)
                ldmx4(ah[mt], uA + (uint32_t)(((wm + mt*16 + aro) * LDSW + kb + ako) * 2));
            #pragma unroll
            for (int ng = 0; ng < 4; ng++) {
                uint32_t bh[4];
                ldmx4(bh, uB + (uint32_t)(((wn + ng*16 + bro) * LDSW + kb + bko) * 2));
                #pragma unroll
                for (int mt = 0; mt < 2; mt++) {
                    mma16816(c[mt][2*ng],   ah[mt], bh[0], bh[1]);
                    mma16816(c[mt][2*ng+1], ah[mt], bh[2], bh[3]);
                }
            }
        }
    }

    #pragma unroll
    for (int mt = 0; mt < 2; mt++) {
        int row = bm + wm + mt * 16 + (lane >> 2);
        #pragma unroll
        for (int nidx = 0; nidx < 8; nidx++) {
            int col = bn + wn + nidx * 8 + (lane & 3) * 2;
            if (row < M)
                *(float2*)(C + (size_t)row * N + col) =
                    make_float2(c[mt][nidx][0], c[mt][nidx][1]);
            if (row + 8 < M)
                *(float2*)(C + (size_t)(row + 8) * N + col) =
                    make_float2(c[mt][nidx][2], c[mt][nidx][3]);
        }
    }
}

// ============ fused gi+gh GEMM + GRU ========================================
// block: 64 rows x 64 gate-cols. 8 warps: wm=(wid&3)*16, wn=(wid>>2)*32.
// 4 accum tiles: r (agg@Wih_r + h@Whh_r), z, i_n (agg@Wih_n), h_n (h@Whh_n).
#define ARRF (64*LDSW)
#define STGF (8*ARRF)
#define SMEM_F (2*STGF*2)

__global__ __launch_bounds__(256)
void gru_fused(const __half* __restrict__ agg16, const __half* __restrict__ h16,
               const float* __restrict__ h32,
               const __half* __restrict__ Wih, const __half* __restrict__ Whh,
               const float* __restrict__ b_ih, const float* __restrict__ b_hh,
               float* __restrict__ h32n, __half* __restrict__ h16n, int M)
{
    extern __shared__ __half smp[];
    const int tid = threadIdx.x, lane = tid & 31, wid = tid >> 5;
    const int bm = blockIdx.y * 64, bn = blockIdx.x * 64;
    const int wm = (wid & 3) * 16, wn = (wid >> 2) * 32;

    float cr[4][4], cz[4][4], cin[4][4], chn[4][4];
    #pragma unroll
    for (int f = 0; f < 4; f++)
        #pragma unroll
        for (int q = 0; q < 4; q++) { cr[f][q]=0.f; cz[f][q]=0.f; cin[f][q]=0.f; chn[f][q]=0.f; }

    // loader: 64 rows, 4 segs of 8 halves. thread t -> row t>>2, seg t&3.
    const int lrow = tid >> 2, lseg = (tid & 3) * 8;
    const __half* pAg = agg16 + (size_t)(bm + lrow) * KP + lseg;
    const __half* pAh = h16   + (size_t)(bm + lrow) * KP + lseg;
    const __half* pW[6];
    pW[0] = Wih + (size_t)(bn + lrow) * KP + lseg;
    pW[1] = Whh + (size_t)(bn + lrow) * KP + lseg;
    pW[2] = Wih + (size_t)(256 + bn + lrow) * KP + lseg;
    pW[3] = Whh + (size_t)(256 + bn + lrow) * KP + lseg;
    pW[4] = Wih + (size_t)(512 + bn + lrow) * KP + lseg;
    pW[5] = Whh + (size_t)(512 + bn + lrow) * KP + lseg;

    const uint32_t u0 = smem_u32(smp);
    const uint32_t ldst = u0 + (uint32_t)(lrow * LDSW + lseg) * 2;

    const int aro = (lane & 7) + ((lane >> 3) & 1) * 8;
    const int ako = ((lane >> 4) & 1) * 8;
    const int bro = (lane & 7) + ((lane >> 4) & 1) * 8;
    const int bko = ((lane >> 3) & 1) * 8;

    // prologue
    cpa16(ldst, pAg);
    cpa16(ldst + (uint32_t)ARRF * 2, pAh);
    #pragma unroll
    for (int s = 0; s < 6; s++)
        cpa16(ldst + (uint32_t)(2 + s) * ARRF * 2, pW[s]);
    cpa_commit();

    for (int ch = 0; ch < 8; ch++) {
        const int cur = ch & 1, nxt = cur ^ 1;
        cpa_wait0();
        __syncthreads();
        if (ch < 7) {
            const int kn = (ch + 1) * 32;
            const uint32_t sb = (uint32_t)(nxt * STGF) * 2;
            cpa16(ldst + sb, pAg + kn);
            cpa16(ldst + sb + (uint32_t)ARRF * 2, pAh + kn);
            #pragma unroll
            for (int s = 0; s < 6; s++)
                cpa16(ldst + sb + (uint32_t)(2 + s) * ARRF * 2, pW[s] + kn);
            cpa_commit();
        }
        const uint32_t base = u0 + (uint32_t)(cur * STGF) * 2;
        #pragma unroll
        for (int kh = 0; kh < 2; kh++) {
            const int kb = kh * 16;
            uint32_t ag[4], ah[4];
            ldmx4(ag, base + (uint32_t)(((wm + aro) * LDSW + kb + ako) * 2));
            ldmx4(ah, base + (uint32_t)ARRF * 2 + (uint32_t)(((wm + aro) * LDSW + kb + ako) * 2));
            const uint32_t bo0 = (uint32_t)(((wn + bro) * LDSW + kb + bko) * 2);
            const uint32_t bo1 = (uint32_t)(((wn + 16 + bro) * LDSW + kb + bko) * 2);
            uint32_t bb[4];
            // r: agg@Wih_r + h@Whh_r
            ldmx4(bb, base + (uint32_t)(2+0)*ARRF*2 + bo0);
            mma16816(cr[0], ag, bb[0], bb[1]); mma16816(cr[1], ag, bb[2], bb[3]);
            ldmx4(bb, base + (uint32_t)(2+0)*ARRF*2 + bo1);
            mma16816(cr[2], ag, bb[0], bb[1]); mma16816(cr[3], ag, bb[2], bb[3]);
            ldmx4(bb, base + (uint32_t)(2+1)*ARRF*2 + bo0);
            mma16816(cr[0], ah, bb[0], bb[1]); mma16816(cr[1], ah, bb[2], bb[3]);
            ldmx4(bb, base + (uint32_t)(2+1)*ARRF*2 + bo1);
            mma16816(cr[2], ah, bb[0], bb[1]); mma16816(cr[3], ah, bb[2], bb[3]);
            // z
            ldmx4(bb, base + (uint32_t)(2+2)*ARRF*2 + bo0);
            mma16816(cz[0], ag, bb[0], bb[1]); mma16816(cz[1], ag, bb[2], bb[3]);
            ldmx4(bb, base + (uint32_t)(2+2)*ARRF*2 + bo1);
            mma16816(cz[2], ag, bb[0], bb[1]); mma16816(cz[3], ag, bb[2], bb[3]);
            ldmx4(bb, base + (uint32_t)(2+3)*ARRF*2 + bo0);
            mma16816(cz[0], ah, bb[0], bb[1]); mma16816(cz[1], ah, bb[2], bb[3]);
            ldmx4(bb, base + (uint32_t)(2+3)*ARRF*2 + bo1);
            mma16816(cz[2], ah, bb[0], bb[1]); mma16816(cz[3], ah, bb[2], bb[3]);
            // i_n (agg), h_n (h)
            ldmx4(bb, base + (uint32_t)(2+4)*ARRF*2 + bo0);
            mma16816(cin[0], ag, bb[0], bb[1]); mma16816(cin[1], ag, bb[2], bb[3]);
            ldmx4(bb, base + (uint32_t)(2+4)*ARRF*2 + bo1);
            mma16816(cin[2], ag, bb[0], bb[1]); mma16816(cin[3], ag, bb[2], bb[3]);
            ldmx4(bb, base + (uint32_t)(2+5)*ARRF*2 + bo0);
            mma16816(chn[0], ah, bb[0], bb[1]); mma16816(chn[1], ah, bb[2], bb[3]);
            ldmx4(bb, base + (uint32_t)(2+5)*ARRF*2 + bo1);
            mma16816(chn[2], ah, bb[0], bb[1]); mma16816(chn[3], ah, bb[2], bb[3]);
        }
    }

    // ---- GRU epilogue ----
    const int r0 = bm + wm + (lane >> 2);
    #pragma unroll
    for (int f = 0; f < 4; f++) {
        const int col = bn + wn + f * 8 + (lane & 3) * 2;
        const float br0 = __ldg(b_ih + col)       + __ldg(b_hh + col);
        const float br1 = __ldg(b_ih + col + 1)   + __ldg(b_hh + col + 1);
        const float bz0 = __ldg(b_ih + 256 + col) + __ldg(b_hh + 256 + col);
        const float bz1 = __ldg(b_ih + 257 + col) + __ldg(b_hh + 257 + col);
        const float bin0 = __ldg(b_ih + 512 + col),   bin1 = __ldg(b_ih + 513 + col);
        const float bhn0 = __ldg(b_hh + 512 + col),   bhn1 = __ldg(b_hh + 513 + col);
        #pragma unroll
        for (int e = 0; e < 2; e++) {
            const int row = r0 + e * 8;
            if (row >= M) continue;
            float2 hv = *(const float2*)(h32 + (size_t)row * HH + col);
            float rr0 = 1.f / (1.f + __expf(-(cr[f][2*e]   + br0)));
            float rr1 = 1.f / (1.f + __expf(-(cr[f][2*e+1] + br1)));
            float zz0 = 1.f / (1.f + __expf(-(cz[f][2*e]   + bz0)));
            float zz1 = 1.f / (1.f + __expf(-(cz[f][2*e+1] + bz1)));
            float nn0 = tanhf(cin[f][2*e]   + bin0 + rr0 * (chn[f][2*e]   + bhn0));
            float nn1 = tanhf(cin[f][2*e+1] + bin1 + rr1 * (chn[f][2*e+1] + bhn1));
            float o0 = (1.f - zz0) * nn0 + zz0 * hv.x;
            float o1 = (1.f - zz1) * nn1 + zz1 * hv.y;
            *(float2*)(h32n + (size_t)row * HH + col) = make_float2(o0, o1);
            *(__half2*)(h16n + (size_t)row * HH + col) = __floats2half2_rn(o0, o1);
        }
    }
}

// ---------------- zero / scatter --------------------------------------------
__global__ void zero_kernel(float4* __restrict__ p, int n4) {
    int t = blockIdx.x * blockDim.x + threadIdx.x;
    if (t < n4) p[t] = make_float4(0.f,0.f,0.f,0.f);
}

__global__ void scatter_kernel(const float* __restrict__ m,
                               const int* __restrict__ src,
                               const int* __restrict__ dst,
                               float* __restrict__ agg)
{
    long long t = (long long)blockIdx.x * blockDim.x + threadIdx.x;
    int e = (int)(t >> 6);
    if (e >= NE) return;
    int c = ((int)t & 63) << 2;
    int s = __ldg(src + e);
    int d = __ldg(dst + e);
    float4 v = *(const float4*)(m + (size_t)s * HH + c);
    float* p = agg + (size_t)d * HH + c;
    asm volatile("red.global.add.v4.f32 [%0], {%1,%2,%3,%4};"
                 :: "l"(p), "f"(v.x), "f"(v.y), "f"(v.z), "f"(v.w) : "memory");
}

// ---------------- head -------------------------------------------------------
__global__ void head_kernel(const float* __restrict__ h,
                            const float* __restrict__ W_lin,
                            const float* __restrict__ b_lin,
                            float* __restrict__ out)
{
    int gw = (blockIdx.x * blockDim.x + threadIdx.x) >> 5;
    int lane = threadIdx.x & 31;
    if (gw >= NN) return;
    const float* hr = h + (size_t)gw * HH;
    float a0 = 0.f, a1 = 0.f;
    #pragma unroll
    for (int k = lane; k < HH; k += 32) {
        float v = hr[k];
        v = v > 0.f ? v : 0.f;
        a0 += v * __ldg(W_lin + k);
        a1 += v * __ldg(W_lin + HH + k);
    }
    #pragma unroll
    for (int off = 16; off; off >>= 1) {
        a0 += __shfl_xor_sync(0xffffffffu, a0, off);
        a1 += __shfl_xor_sync(0xffffffffu, a1, off);
    }
    if (lane == 0) {
        float o0 = a0 + b_lin[0];
        float o1 = a1 + b_lin[1];
        float mx = fmaxf(o0, o1);
        float lse = mx + logf(expf(o0 - mx) + expf(o1 - mx));
        out[2*gw]     = o0 - lse;
        out[2*gw + 1] = o1 - lse;
    }
}

// ---------------- launch -----------------------------------------------------
extern "C" void kernel_launch(void* const* d_in, const int* in_sizes, int n_in,
                              void* d_out, int out_size)
{
    const float* x        = (const float*)d_in[0];
    const int*   edge     = (const int*)  d_in[1];
    const float* W_reduce = (const float*)d_in[3];
    const float* b_reduce = (const float*)d_in[4];
    const float* W_ggc    = (const float*)d_in[5];
    const float* W_ih     = (const float*)d_in[6];
    const float* W_hh     = (const float*)d_in[7];
    const float* b_ih     = (const float*)d_in[8];
    const float* b_hh     = (const float*)d_in[9];
    const float* W_lin    = (const float*)d_in[10];
    const float* b_lin    = (const float*)d_in[11];
    float* out = (float*)d_out;

    const int* src = edge;
    const int* dst = edge + NE;

    float *h0, *h1, *mbuf, *agg;
    __half *h16a, *h16b, *agg16, *wred, *wggc, *wih, *whh;
    cudaGetSymbolAddress((void**)&h0,    g_h0);
    cudaGetSymbolAddress((void**)&h1,    g_h1);
    cudaGetSymbolAddress((void**)&mbuf,  g_m);
    cudaGetSymbolAddress((void**)&agg,   g_agg);
    cudaGetSymbolAddress((void**)&h16a,  g_h16a);
    cudaGetSymbolAddress((void**)&h16b,  g_h16b);
    cudaGetSymbolAddress((void**)&agg16, g_agg16);
    cudaGetSymbolAddress((void**)&wred,  g_wred);
    cudaGetSymbolAddress((void**)&wggc,  g_wggc);
    cudaGetSymbolAddress((void**)&wih,   g_wih);
    cudaGetSymbolAddress((void**)&whh,   g_whh);

    cudaFuncSetAttribute(mma_gemm,   cudaFuncAttributeMaxDynamicSharedMemorySize, SMEM_G);
    cudaFuncSetAttribute(mma_gemm16, cudaFuncAttributeMaxDynamicSharedMemorySize, SMEM_G);
    cudaFuncSetAttribute(gru_fused,  cudaFuncAttributeMaxDynamicSharedMemorySize, SMEM_F);

    conv_w<<<(HH*KP + 255)/256, 256>>>(W_reduce, wred, HH, 200);
    conv_w<<<(H3*KP + 255)/256, 256>>>(W_ih, wih, H3, KP);
    conv_w<<<(H3*KP + 255)/256, 256>>>(W_hh, whh, H3, KP);
    conv_wggcT<<<(8*HH*KP + 255)/256, 256>>>(W_ggc, wggc);

    const int mtiles128 = (NN + 127) / 128;   // 391
    const int mtiles64  = (NN + 63) / 64;     // 782
    const int n8 = NN * HH / 8;

    // h = x @ W_reduce^T + b_reduce ; fp16 shadow
    mma_gemm<<<dim3(HH/128, mtiles128), 256, SMEM_G>>>(x, wred, b_reduce, h0, NN, HH, 200);
    cvt16<<<(n8 + 255)/256, 256>>>(h0, h16a, n8);

    float *hc32 = h0, *hn32 = h1;
    __half *hc16 = h16a, *hn16 = h16b;
    for (int s = 0; s < 8; s++) {
        mma_gemm16<<<dim3(HH/128, mtiles128), 256, SMEM_G>>>(hc16, wggc + (size_t)s*HH*KP, mbuf, NN, HH);
        zero_kernel<<<(NN*HH/4 + 255)/256, 256>>>((float4*)agg, NN*HH/4);
        scatter_kernel<<<((long long)NE*64 + 255)/256, 256>>>(mbuf, src, dst, agg);
        cvt16<<<(n8 + 255)/256, 256>>>(agg, agg16, n8);
        gru_fused<<<dim3(HH/64, mtiles64), 256, SMEM_F>>>(agg16, hc16, hc32, wih, whh,
                                                          b_ih, b_hh, hn32, hn16, NN);
        { float* t = hc32; hc32 = hn32; hn32 = t; }
        { __half* t = hc16; hc16 = hn16; hn16 = t; }
    }

    head_kernel<<<(NN*32 + 255)/256, 256>>>(hc32, W_lin, b_lin, out);
}

// round 9
// speedup vs baseline: 4.1656x; 1.0906x over previous
#include <cuda_runtime.h>
#include <cuda_fp16.h>
#include <math.h>
#include <stdint.h>

#define NN 50000
#define HH 256
#define NE 300000
#define H3 (3*HH)
#define KP 256
#define NPAD (NN + 128)

// ---------------- scratch ----------------------------------------------------
__device__ float g_h0[NN*HH];
__device__ float g_h1[NN*HH];
__device__ float g_m [NN*HH];
__device__ float g_agg[NN*HH];
__device__ __half g_h16a[(size_t)NPAD*HH];
__device__ __half g_h16b[(size_t)NPAD*HH];

// fp16 weights, [rows, 256] K-major
__device__ __half g_wred[HH*KP];
__device__ __half g_wggc[8*HH*KP];
__device__ __half g_wih[H3*KP];
__device__ __half g_whh[H3*KP];

// ---------------- weight conversion ------------------------------------------
__global__ void conv_w(const float* __restrict__ W, __half* __restrict__ o,
                       int Nrows, int Ksrc)
{
    int t = blockIdx.x * blockDim.x + threadIdx.x;
    if (t >= Nrows * KP) return;
    int n = t >> 8, k = t & 255;
    float v = (k < Ksrc) ? W[(size_t)n * Ksrc + k] : 0.f;
    o[t] = __float2half_rn(v);
}

__global__ void conv_wggcT(const float* __restrict__ W, __half* __restrict__ o)
{
    int t = blockIdx.x * blockDim.x + threadIdx.x;
    if (t >= 8 * HH * KP) return;
    int s = t >> 16, n = (t >> 8) & 255, k = t & 255;
    o[t] = __float2half_rn(W[((size_t)s << 16) + (size_t)k * HH + n]);
}

__global__ void cvt16(const float* __restrict__ in, __half* __restrict__ o, int n8) {
    int t = blockIdx.x * blockDim.x + threadIdx.x;
    if (t >= n8) return;
    float4 a = *(const float4*)(in + t * 8);
    float4 b = *(const float4*)(in + t * 8 + 4);
    __half2 h[4];
    h[0] = __floats2half2_rn(a.x, a.y);
    h[1] = __floats2half2_rn(a.z, a.w);
    h[2] = __floats2half2_rn(b.x, b.y);
    h[3] = __floats2half2_rn(b.z, b.w);
    *(uint4*)(o + t * 8) = *(uint4*)h;
}

// ---------------- asm helpers ------------------------------------------------
__device__ __forceinline__ uint32_t smem_u32(const void* p) {
    uint32_t a;
    asm("{ .reg .u64 t; cvta.to.shared.u64 t, %1; cvt.u32.u64 %0, t; }" : "=r"(a) : "l"(p));
    return a;
}
__device__ __forceinline__ void ldmx4(uint32_t* r, uint32_t addr) {
    asm volatile("ldmatrix.sync.aligned.m8n8.x4.shared.b16 {%0,%1,%2,%3}, [%4];"
                 : "=r"(r[0]), "=r"(r[1]), "=r"(r[2]), "=r"(r[3]) : "r"(addr));
}
__device__ __forceinline__ void mma16816(float* d, const uint32_t* a, uint32_t b0, uint32_t b1) {
    asm volatile(
        "mma.sync.aligned.m16n8k16.row.col.f32.f16.f16.f32 "
        "{%0,%1,%2,%3}, {%4,%5,%6,%7}, {%8,%9}, {%0,%1,%2,%3};"
        : "+f"(d[0]), "+f"(d[1]), "+f"(d[2]), "+f"(d[3])
        : "r"(a[0]), "r"(a[1]), "r"(a[2]), "r"(a[3]), "r"(b0), "r"(b1));
}
__device__ __forceinline__ void cpa16(uint32_t dst, const void* src) {
    asm volatile("cp.async.ca.shared.global [%0], [%1], 16;" :: "r"(dst), "l"(src) : "memory");
}
__device__ __forceinline__ void cpa_commit() {
    asm volatile("cp.async.commit_group;" ::: "memory");
}
__device__ __forceinline__ void cpa_wait0() {
    asm volatile("cp.async.wait_group 0;" ::: "memory");
}

#define LDSW 40

// ============ GEMM A=fp32 (reduce): C = A @ B^T + bias ======================
#define ARR (128*LDSW)
#define STG (2*ARR)
#define SMEM_G (2*STG*2)

__global__ __launch_bounds__(256)
void mma_gemm(const float* __restrict__ A, const __half* __restrict__ B,
              const float* __restrict__ bias, float* __restrict__ C,
              int M, int N, int Ksrc)
{
    extern __shared__ __half smp[];
    const int tid = threadIdx.x, lane = tid & 31, wid = tid >> 5;
    const int bm = blockIdx.y * 128, bn = blockIdx.x * 128;
    const int wm = (wid & 3) * 32, wn = (wid >> 2) * 64;

    float c[2][8][4];
    #pragma unroll
    for (int i = 0; i < 2; i++)
        #pragma unroll
        for (int j = 0; j < 8; j++)
            #pragma unroll
            for (int q = 0; q < 4; q++) c[i][j][q] = 0.f;

    const int lrow = tid >> 1, lcol = (tid & 1) * 16;
    const bool rv = (bm + lrow) < M;
    const float* Arow = A + (size_t)(bm + lrow) * Ksrc + lcol;
    const __half* Brow = B + (size_t)(bn + lrow) * KP + lcol;

    const uint32_t u0 = smem_u32(smp);
    const int lodst = lrow * LDSW + lcol;
    const uint32_t bdst = u0 + (uint32_t)(ARR + lodst) * 2;

    const int aro = (lane & 7) + ((lane >> 3) & 1) * 8;
    const int ako = ((lane >> 4) & 1) * 8;
    const int bro = (lane & 7) + ((lane >> 4) & 1) * 8;
    const int bko = ((lane >> 3) & 1) * 8;

    {
        #pragma unroll
        for (int q = 0; q < 4; q++) {
            int k = lcol + q * 4;
            float4 v = make_float4(0.f,0.f,0.f,0.f);
            if (rv && k < Ksrc) v = *(const float4*)(Arow + q * 4);
            __half2 p0 = __floats2half2_rn(v.x, v.y);
            __half2 p1 = __floats2half2_rn(v.z, v.w);
            int o = lodst + q * 4;
            *(__half2*)&smp[o] = p0; *(__half2*)&smp[o+2] = p1;
        }
        cpa16(bdst, Brow); cpa16(bdst + 16, Brow + 8);
        cpa_commit();
    }

    for (int ch = 0; ch < 8; ch++) {
        const int cur = ch & 1, nxt = cur ^ 1;
        cpa_wait0();
        __syncthreads();
        float ar[16];
        if (ch < 7) {
            const int kn = (ch + 1) * 32;
            #pragma unroll
            for (int q = 0; q < 4; q++) {
                int k = kn + lcol + q * 4;
                float4 v = make_float4(0.f,0.f,0.f,0.f);
                if (rv && k < Ksrc) v = *(const float4*)(Arow + kn + q * 4);
                ar[q*4+0]=v.x; ar[q*4+1]=v.y; ar[q*4+2]=v.z; ar[q*4+3]=v.w;
            }
            const uint32_t sb = (uint32_t)(nxt * STG) * 2;
            cpa16(bdst + sb, Brow + kn); cpa16(bdst + sb + 16, Brow + kn + 8);
            cpa_commit();
        }
        const uint32_t base = u0 + (uint32_t)(cur * STG) * 2;
        const uint32_t uA = base, uB = base + ARR * 2;
        #pragma unroll
        for (int kh = 0; kh < 2; kh++) {
            const int kb = kh * 16;
            uint32_t ah[2][4];
            #pragma unroll
            for (int mt = 0; mt < 2; mt++)
                ldmx4(ah[mt], uA + (uint32_t)(((wm + mt*16 + aro) * LDSW + kb + ako) * 2));
            #pragma unroll
            for (int ng = 0; ng < 4; ng++) {
                uint32_t bh[4];
                ldmx4(bh, uB + (uint32_t)(((wn + ng*16 + bro) * LDSW + kb + bko) * 2));
                #pragma unroll
                for (int mt = 0; mt < 2; mt++) {
                    mma16816(c[mt][2*ng],   ah[mt], bh[0], bh[1]);
                    mma16816(c[mt][2*ng+1], ah[mt], bh[2], bh[3]);
                }
            }
        }
        if (ch < 7) {
            __half* sA = smp + nxt * STG;
            #pragma unroll
            for (int q = 0; q < 4; q++) {
                __half2 p0 = __floats2half2_rn(ar[q*4+0], ar[q*4+1]);
                __half2 p1 = __floats2half2_rn(ar[q*4+2], ar[q*4+3]);
                int o = lodst + q * 4;
                *(__half2*)&sA[o] = p0; *(__half2*)&sA[o+2] = p1;
            }
        }
    }

    #pragma unroll
    for (int mt = 0; mt < 2; mt++) {
        int row = bm + wm + mt * 16 + (lane >> 2);
        #pragma unroll
        for (int nidx = 0; nidx < 8; nidx++) {
            int col = bn + wn + nidx * 8 + (lane & 3) * 2;
            float b0 = 0.f, b1 = 0.f;
            if (bias) { b0 = bias[col]; b1 = bias[col + 1]; }
            if (row < M)
                *(float2*)(C + (size_t)row * N + col) =
                    make_float2(c[mt][nidx][0] + b0, c[mt][nidx][1] + b1);
            if (row + 8 < M)
                *(float2*)(C + (size_t)(row + 8) * N + col) =
                    make_float2(c[mt][nidx][2] + b0, c[mt][nidx][3] + b1);
        }
    }
}

// ============ GEMM A=fp16 (ggc): C = A @ B^T ================================
__global__ __launch_bounds__(256)
void mma_gemm16(const __half* __restrict__ A, const __half* __restrict__ B,
                float* __restrict__ C, int M, int N)
{
    extern __shared__ __half smp[];
    const int tid = threadIdx.x, lane = tid & 31, wid = tid >> 5;
    const int bm = blockIdx.y * 128, bn = blockIdx.x * 128;
    const int wm = (wid & 3) * 32, wn = (wid >> 2) * 64;

    float c[2][8][4];
    #pragma unroll
    for (int i = 0; i < 2; i++)
        #pragma unroll
        for (int j = 0; j < 8; j++)
            #pragma unroll
            for (int q = 0; q < 4; q++) c[i][j][q] = 0.f;

    const int lrow = tid >> 1, lcol = (tid & 1) * 16;
    const __half* Arow = A + (size_t)(bm + lrow) * KP + lcol;
    const __half* Brow = B + (size_t)(bn + lrow) * KP + lcol;

    const uint32_t u0 = smem_u32(smp);
    const int lodst = lrow * LDSW + lcol;
    const uint32_t adst = u0 + (uint32_t)lodst * 2;
    const uint32_t bdst = u0 + (uint32_t)(ARR + lodst) * 2;

    const int aro = (lane & 7) + ((lane >> 3) & 1) * 8;
    const int ako = ((lane >> 4) & 1) * 8;
    const int bro = (lane & 7) + ((lane >> 4) & 1) * 8;
    const int bko = ((lane >> 3) & 1) * 8;

    cpa16(adst, Arow); cpa16(adst + 16, Arow + 8);
    cpa16(bdst, Brow); cpa16(bdst + 16, Brow + 8);
    cpa_commit();

    for (int ch = 0; ch < 8; ch++) {
        const int cur = ch & 1, nxt = cur ^ 1;
        cpa_wait0();
        __syncthreads();
        if (ch < 7) {
            const int kn = (ch + 1) * 32;
            const uint32_t sb = (uint32_t)(nxt * STG) * 2;
            cpa16(adst + sb, Arow + kn); cpa16(adst + sb + 16, Arow + kn + 8);
            cpa16(bdst + sb, Brow + kn); cpa16(bdst + sb + 16, Brow + kn + 8);
            cpa_commit();
        }
        const uint32_t base = u0 + (uint32_t)(cur * STG) * 2;
        const uint32_t uA = base, uB = base + ARR * 2;
        #pragma unroll
        for (int kh = 0; kh < 2; kh++) {
            const int kb = kh * 16;
            uint32_t ah[2][4];
            #pragma unroll
            for (int mt = 0; mt < 2; mt++)
                ldmx4(ah[mt], uA + (uint32_t)(((wm + mt*16 + aro) * LDSW + kb + ako) * 2));
            #pragma unroll
            for (int ng = 0; ng < 4; ng++) {
                uint32_t bh[4];
                ldmx4(bh, uB + (uint32_t)(((wn + ng*16 + bro) * LDSW + kb + bko) * 2));
                #pragma unroll
                for (int mt = 0; mt < 2; mt++) {
                    mma16816(c[mt][2*ng],   ah[mt], bh[0], bh[1]);
                    mma16816(c[mt][2*ng+1], ah[mt], bh[2], bh[3]);
                }
            }
        }
    }

    #pragma unroll
    for (int mt = 0; mt < 2; mt++) {
        int row = bm + wm + mt * 16 + (lane >> 2);
        #pragma unroll
        for (int nidx = 0; nidx < 8; nidx++) {
            int col = bn + wn + nidx * 8 + (lane & 3) * 2;
            if (row < M)
                *(float2*)(C + (size_t)row * N + col) =
                    make_float2(c[mt][nidx][0], c[mt][nidx][1]);
            if (row + 8 < M)
                *(float2*)(C + (size_t)(row + 8) * N + col) =
                    make_float2(c[mt][nidx][2], c[mt][nidx][3]);
        }
    }
}

// ============ fused gi+gh GEMM + GRU ========================================
// block 128 rows x 64 gate-cols; warps 4(M) x 2(N); warp tile 32x32.
// Accum tiles: r = agg@Wih_r + h@Whh_r ; z likewise ; i_n = agg@Wih_n ; h_n = h@Whh_n.
// smem per stage: Ag[128xLDSW] (fp32->fp16 in-kernel), Ah[128xLDSW] (cp.async),
//                 W0..W5[64xLDSW] (cp.async).
#define ARRA (128*LDSW)
#define ARRW (64*LDSW)
#define STGF (2*ARRA + 6*ARRW)
#define SMEM_F (2*STGF*2)

__global__ __launch_bounds__(256)
void gru_fused(const float* __restrict__ agg32, const __half* __restrict__ h16,
               const float* __restrict__ h32,
               const __half* __restrict__ Wih, const __half* __restrict__ Whh,
               const float* __restrict__ b_ih, const float* __restrict__ b_hh,
               float* __restrict__ h32n, __half* __restrict__ h16n, int M)
{
    extern __shared__ __half smp[];
    const int tid = threadIdx.x, lane = tid & 31, wid = tid >> 5;
    const int bm = blockIdx.y * 128, bn = blockIdx.x * 64;
    const int wm = (wid & 3) * 32, wn = (wid >> 2) * 32;

    float cr[2][4][4], cz[2][4][4], cin[2][4][4], chn[2][4][4];
    #pragma unroll
    for (int mt = 0; mt < 2; mt++)
        #pragma unroll
        for (int f = 0; f < 4; f++)
            #pragma unroll
            for (int q = 0; q < 4; q++)
            { cr[mt][f][q]=0.f; cz[mt][f][q]=0.f; cin[mt][f][q]=0.f; chn[mt][f][q]=0.f; }

    // A loader: row = tid>>1 (0..127), 16-col seg at (tid&1)*16
    const int arow = tid >> 1, aseg = (tid & 1) * 16;
    const bool rv = (bm + arow) < M;
    const float* pAg = agg32 + (size_t)(bm + arow) * HH + aseg;
    const __half* pAh = h16   + (size_t)(bm + arow) * KP + aseg;
    // W loader: row = tid>>2 (0..63), 8-col seg at (tid&3)*8
    const int wrow = tid >> 2, wseg = (tid & 3) * 8;
    const __half* pW[6];
    pW[0] = Wih + (size_t)(bn + wrow) * KP + wseg;
    pW[1] = Whh + (size_t)(bn + wrow) * KP + wseg;
    pW[2] = Wih + (size_t)(256 + bn + wrow) * KP + wseg;
    pW[3] = Whh + (size_t)(256 + bn + wrow) * KP + wseg;
    pW[4] = Wih + (size_t)(512 + bn + wrow) * KP + wseg;
    pW[5] = Whh + (size_t)(512 + bn + wrow) * KP + wseg;

    const uint32_t u0 = smem_u32(smp);
    const int aodst = arow * LDSW + aseg;
    const uint32_t ahdst = u0 + (uint32_t)(ARRA + aodst) * 2;
    const uint32_t wdst0 = u0 + (uint32_t)(2*ARRA + wrow * LDSW + wseg) * 2;

    const int aro = (lane & 7) + ((lane >> 3) & 1) * 8;
    const int ako = ((lane >> 4) & 1) * 8;
    const int bro = (lane & 7) + ((lane >> 4) & 1) * 8;
    const int bko = ((lane >> 3) & 1) * 8;

    // prologue: chunk 0
    {
        #pragma unroll
        for (int q = 0; q < 4; q++) {
            float4 v = rv ? *(const float4*)(pAg + q * 4) : make_float4(0.f,0.f,0.f,0.f);
            __half2 p0 = __floats2half2_rn(v.x, v.y);
            __half2 p1 = __floats2half2_rn(v.z, v.w);
            int o = aodst + q * 4;
            *(__half2*)&smp[o] = p0; *(__half2*)&smp[o+2] = p1;
        }
        cpa16(ahdst, pAh); cpa16(ahdst + 16, pAh + 8);
        #pragma unroll
        for (int s = 0; s < 6; s++)
            cpa16(wdst0 + (uint32_t)(s * ARRW) * 2, pW[s]);
        cpa_commit();
    }

    for (int ch = 0; ch < 8; ch++) {
        const int cur = ch & 1, nxt = cur ^ 1;
        cpa_wait0();
        __syncthreads();
        float ar[16];
        if (ch < 7) {
            const int kn = (ch + 1) * 32;
            #pragma unroll
            for (int q = 0; q < 4; q++) {
                float4 v = rv ? *(const float4*)(pAg + kn + q * 4) : make_float4(0.f,0.f,0.f,0.f);
                ar[q*4+0]=v.x; ar[q*4+1]=v.y; ar[q*4+2]=v.z; ar[q*4+3]=v.w;
            }
            const uint32_t sb = (uint32_t)(nxt * STGF) * 2;
            cpa16(ahdst + sb, pAh + kn); cpa16(ahdst + sb + 16, pAh + kn + 8);
            #pragma unroll
            for (int s = 0; s < 6; s++)
                cpa16(wdst0 + sb + (uint32_t)(s * ARRW) * 2, pW[s] + kn);
            cpa_commit();
        }

        const uint32_t base = u0 + (uint32_t)(cur * STGF) * 2;
        const uint32_t uAg = base, uAh = base + (uint32_t)ARRA * 2;
        #pragma unroll
        for (int kh = 0; kh < 2; kh++) {
            const int kb = kh * 16;
            uint32_t ag[2][4], ah[2][4];
            #pragma unroll
            for (int mt = 0; mt < 2; mt++) {
                const uint32_t ao = (uint32_t)(((wm + mt*16 + aro) * LDSW + kb + ako) * 2);
                ldmx4(ag[mt], uAg + ao);
                ldmx4(ah[mt], uAh + ao);
            }
            #pragma unroll
            for (int ng = 0; ng < 2; ng++) {
                const uint32_t bo = (uint32_t)(((wn + ng*16 + bro) * LDSW + kb + bko) * 2);
                uint32_t bb[4];
                // r gate
                ldmx4(bb, base + (uint32_t)(2*ARRA + 0*ARRW) * 2 + bo);
                #pragma unroll
                for (int mt = 0; mt < 2; mt++) {
                    mma16816(cr[mt][2*ng],   ag[mt], bb[0], bb[1]);
                    mma16816(cr[mt][2*ng+1], ag[mt], bb[2], bb[3]);
                }
                ldmx4(bb, base + (uint32_t)(2*ARRA + 1*ARRW) * 2 + bo);
                #pragma unroll
                for (int mt = 0; mt < 2; mt++) {
                    mma16816(cr[mt][2*ng],   ah[mt], bb[0], bb[1]);
                    mma16816(cr[mt][2*ng+1], ah[mt], bb[2], bb[3]);
                }
                // z gate
                ldmx4(bb, base + (uint32_t)(2*ARRA + 2*ARRW) * 2 + bo);
                #pragma unroll
                for (int mt = 0; mt < 2; mt++) {
                    mma16816(cz[mt][2*ng],   ag[mt], bb[0], bb[1]);
                    mma16816(cz[mt][2*ng+1], ag[mt], bb[2], bb[3]);
                }
                ldmx4(bb, base + (uint32_t)(2*ARRA + 3*ARRW) * 2 + bo);
                #pragma unroll
                for (int mt = 0; mt < 2; mt++) {
                    mma16816(cz[mt][2*ng],   ah[mt], bb[0], bb[1]);
                    mma16816(cz[mt][2*ng+1], ah[mt], bb[2], bb[3]);
                }
                // i_n (agg only)
                ldmx4(bb, base + (uint32_t)(2*ARRA + 4*ARRW) * 2 + bo);
                #pragma unroll
                for (int mt = 0; mt < 2; mt++) {
                    mma16816(cin[mt][2*ng],   ag[mt], bb[0], bb[1]);
                    mma16816(cin[mt][2*ng+1], ag[mt], bb[2], bb[3]);
                }
                // h_n (h only)
                ldmx4(bb, base + (uint32_t)(2*ARRA + 5*ARRW) * 2 + bo);
                #pragma unroll
                for (int mt = 0; mt < 2; mt++) {
                    mma16816(chn[mt][2*ng],   ah[mt], bb[0], bb[1]);
                    mma16816(chn[mt][2*ng+1], ah[mt], bb[2], bb[3]);
                }
            }
        }

        if (ch < 7) {
            __half* sA = smp + nxt * STGF;
            #pragma unroll
            for (int q = 0; q < 4; q++) {
                __half2 p0 = __floats2half2_rn(ar[q*4+0], ar[q*4+1]);
                __half2 p1 = __floats2half2_rn(ar[q*4+2], ar[q*4+3]);
                int o = aodst + q * 4;
                *(__half2*)&sA[o] = p0; *(__half2*)&sA[o+2] = p1;
            }
        }
    }

    // ---- GRU epilogue ----
    #pragma unroll
    for (int mt = 0; mt < 2; mt++) {
        const int r0 = bm + wm + mt * 16 + (lane >> 2);
        #pragma unroll
        for (int f = 0; f < 4; f++) {
            const int col = bn + wn + f * 8 + (lane & 3) * 2;
            const float br0 = __ldg(b_ih + col)       + __ldg(b_hh + col);
            const float br1 = __ldg(b_ih + col + 1)   + __ldg(b_hh + col + 1);
            const float bz0 = __ldg(b_ih + 256 + col) + __ldg(b_hh + 256 + col);
            const float bz1 = __ldg(b_ih + 257 + col) + __ldg(b_hh + 257 + col);
            const float bin0 = __ldg(b_ih + 512 + col),   bin1 = __ldg(b_ih + 513 + col);
            const float bhn0 = __ldg(b_hh + 512 + col),   bhn1 = __ldg(b_hh + 513 + col);
            #pragma unroll
            for (int e = 0; e < 2; e++) {
                const int row = r0 + e * 8;
                if (row >= M) continue;
                float2 hv = *(const float2*)(h32 + (size_t)row * HH + col);
                float rr0 = 1.f / (1.f + __expf(-(cr[mt][f][2*e]   + br0)));
                float rr1 = 1.f / (1.f + __expf(-(cr[mt][f][2*e+1] + br1)));
                float zz0 = 1.f / (1.f + __expf(-(cz[mt][f][2*e]   + bz0)));
                float zz1 = 1.f / (1.f + __expf(-(cz[mt][f][2*e+1] + bz1)));
                float nn0 = tanhf(cin[mt][f][2*e]   + bin0 + rr0 * (chn[mt][f][2*e]   + bhn0));
                float nn1 = tanhf(cin[mt][f][2*e+1] + bin1 + rr1 * (chn[mt][f][2*e+1] + bhn1));
                float o0 = (1.f - zz0) * nn0 + zz0 * hv.x;
                float o1 = (1.f - zz1) * nn1 + zz1 * hv.y;
                *(float2*)(h32n + (size_t)row * HH + col) = make_float2(o0, o1);
                *(__half2*)(h16n + (size_t)row * HH + col) = __floats2half2_rn(o0, o1);
            }
        }
    }
}

// ---------------- zero / scatter --------------------------------------------
__global__ void zero_kernel(float4* __restrict__ p, int n4) {
    int t = blockIdx.x * blockDim.x + threadIdx.x;
    if (t < n4) p[t] = make_float4(0.f,0.f,0.f,0.f);
}

__global__ void scatter_kernel(const float* __restrict__ m,
                               const int* __restrict__ src,
                               const int* __restrict__ dst,
                               float* __restrict__ agg)
{
    long long t = (long long)blockIdx.x * blockDim.x + threadIdx.x;
    int e = (int)(t >> 6);
    if (e >= NE) return;
    int c = ((int)t & 63) << 2;
    int s = __ldg(src + e);
    int d = __ldg(dst + e);
    float4 v = *(const float4*)(m + (size_t)s * HH + c);
    float* p = agg + (size_t)d * HH + c;
    asm volatile("red.global.add.v4.f32 [%0], {%1,%2,%3,%4};"
                 :: "l"(p), "f"(v.x), "f"(v.y), "f"(v.z), "f"(v.w) : "memory");
}

// ---------------- head -------------------------------------------------------
__global__ void head_kernel(const float* __restrict__ h,
                            const float* __restrict__ W_lin,
                            const float* __restrict__ b_lin,
                            float* __restrict__ out)
{
    int gw = (blockIdx.x * blockDim.x + threadIdx.x) >> 5;
    int lane = threadIdx.x & 31;
    if (gw >= NN) return;
    const float* hr = h + (size_t)gw * HH;
    float a0 = 0.f, a1 = 0.f;
    #pragma unroll
    for (int k = lane; k < HH; k += 32) {
        float v = hr[k];
        v = v > 0.f ? v : 0.f;
        a0 += v * __ldg(W_lin + k);
        a1 += v * __ldg(W_lin + HH + k);
    }
    #pragma unroll
    for (int off = 16; off; off >>= 1) {
        a0 += __shfl_xor_sync(0xffffffffu, a0, off);
        a1 += __shfl_xor_sync(0xffffffffu, a1, off);
    }
    if (lane == 0) {
        float o0 = a0 + b_lin[0];
        float o1 = a1 + b_lin[1];
        float mx = fmaxf(o0, o1);
        float lse = mx + logf(expf(o0 - mx) + expf(o1 - mx));
        out[2*gw]     = o0 - lse;
        out[2*gw + 1] = o1 - lse;
    }
}

// ---------------- launch -----------------------------------------------------
extern "C" void kernel_launch(void* const* d_in, const int* in_sizes, int n_in,
                              void* d_out, int out_size)
{
    const float* x        = (const float*)d_in[0];
    const int*   edge     = (const int*)  d_in[1];
    const float* W_reduce = (const float*)d_in[3];
    const float* b_reduce = (const float*)d_in[4];
    const float* W_ggc    = (const float*)d_in[5];
    const float* W_ih     = (const float*)d_in[6];
    const float* W_hh     = (const float*)d_in[7];
    const float* b_ih     = (const float*)d_in[8];
    const float* b_hh     = (const float*)d_in[9];
    const float* W_lin    = (const float*)d_in[10];
    const float* b_lin    = (const float*)d_in[11];
    float* out = (float*)d_out;

    const int* src = edge;
    const int* dst = edge + NE;

    float *h0, *h1, *mbuf, *agg;
    __half *h16a, *h16b, *wred, *wggc, *wih, *whh;
    cudaGetSymbolAddress((void**)&h0,    g_h0);
    cudaGetSymbolAddress((void**)&h1,    g_h1);
    cudaGetSymbolAddress((void**)&mbuf,  g_m);
    cudaGetSymbolAddress((void**)&agg,   g_agg);
    cudaGetSymbolAddress((void**)&h16a,  g_h16a);
    cudaGetSymbolAddress((void**)&h16b,  g_h16b);
    cudaGetSymbolAddress((void**)&wred,  g_wred);
    cudaGetSymbolAddress((void**)&wggc,  g_wggc);
    cudaGetSymbolAddress((void**)&wih,   g_wih);
    cudaGetSymbolAddress((void**)&whh,   g_whh);

    cudaFuncSetAttribute(mma_gemm,   cudaFuncAttributeMaxDynamicSharedMemorySize, SMEM_G);
    cudaFuncSetAttribute(mma_gemm16, cudaFuncAttributeMaxDynamicSharedMemorySize, SMEM_G);
    cudaFuncSetAttribute(gru_fused,  cudaFuncAttributeMaxDynamicSharedMemorySize, SMEM_F);

    conv_w<<<(HH*KP + 255)/256, 256>>>(W_reduce, wred, HH, 200);
    conv_w<<<(H3*KP + 255)/256, 256>>>(W_ih, wih, H3, KP);
    conv_w<<<(H3*KP + 255)/256, 256>>>(W_hh, whh, H3, KP);
    conv_wggcT<<<(8*HH*KP + 255)/256, 256>>>(W_ggc, wggc);

    const int mtiles128 = (NN + 127) / 128;   // 391
    const int n8 = NN * HH / 8;

    mma_gemm<<<dim3(HH/128, mtiles128), 256, SMEM_G>>>(x, wred, b_reduce, h0, NN, HH, 200);
    cvt16<<<(n8 + 255)/256, 256>>>(h0, h16a, n8);

    float *hc32 = h0, *hn32 = h1;
    __half *hc16 = h16a, *hn16 = h16b;
    for (int s = 0; s < 8; s++) {
        mma_gemm16<<<dim3(HH/128, mtiles128), 256, SMEM_G>>>(hc16, wggc + (size_t)s*HH*KP, mbuf, NN, HH);
        zero_kernel<<<(NN*HH/4 + 255)/256, 256>>>((float4*)agg, NN*HH/4);
        scatter_kernel<<<((long long)NE*64 + 255)/256, 256>>>(mbuf, src, dst, agg);
        gru_fused<<<dim3(HH/64, mtiles128), 256, SMEM_F>>>(agg, hc16, hc32, wih, whh,
                                                           b_ih, b_hh, hn32, hn16, NN);
        { float* t = hc32; hc32 = hn32; hn32 = t; }
        { __half* t = hc16; hc16 = hn16; hn16 = t; }
    }

    head_kernel<<<(NN*32 + 255)/256, 256>>>(hc32, W_lin, b_lin, out);
}

// round 10
// speedup vs baseline: 4.2669x; 1.0243x over previous
#include <cuda_runtime.h>
#include <cuda_fp16.h>
#include <math.h>
#include <stdint.h>

#define NN 50000
#define HH 256
#define NE 300000
#define H3 (3*HH)
#define KP 256
#define NPAD (NN + 128)

// ---------------- scratch ----------------------------------------------------
__device__ float g_h0[NN*HH];
__device__ float g_h1[NN*HH];
__device__ float g_agg[NN*HH];
__device__ __half g_m16[(size_t)NN*HH];
__device__ __half g_h16a[(size_t)NPAD*HH];
__device__ __half g_h16b[(size_t)NPAD*HH];

// fp16 weights, [rows, 256] K-major
__device__ __half g_wred[HH*KP];
__device__ __half g_wggc[8*HH*KP];
__device__ __half g_wih[H3*KP];
__device__ __half g_whh[H3*KP];

// ---------------- weight conversion ------------------------------------------
__global__ void conv_w(const float* __restrict__ W, __half* __restrict__ o,
                       int Nrows, int Ksrc)
{
    int t = blockIdx.x * blockDim.x + threadIdx.x;
    if (t >= Nrows * KP) return;
    int n = t >> 8, k = t & 255;
    float v = (k < Ksrc) ? W[(size_t)n * Ksrc + k] : 0.f;
    o[t] = __float2half_rn(v);
}

__global__ void conv_wggcT(const float* __restrict__ W, __half* __restrict__ o)
{
    int t = blockIdx.x * blockDim.x + threadIdx.x;
    if (t >= 8 * HH * KP) return;
    int s = t >> 16, n = (t >> 8) & 255, k = t & 255;
    o[t] = __float2half_rn(W[((size_t)s << 16) + (size_t)k * HH + n]);
}

// ---------------- asm helpers ------------------------------------------------
__device__ __forceinline__ uint32_t smem_u32(const void* p) {
    uint32_t a;
    asm("{ .reg .u64 t; cvta.to.shared.u64 t, %1; cvt.u32.u64 %0, t; }" : "=r"(a) : "l"(p));
    return a;
}
__device__ __forceinline__ void ldmx4(uint32_t* r, uint32_t addr) {
    asm volatile("ldmatrix.sync.aligned.m8n8.x4.shared.b16 {%0,%1,%2,%3}, [%4];"
                 : "=r"(r[0]), "=r"(r[1]), "=r"(r[2]), "=r"(r[3]) : "r"(addr));
}
__device__ __forceinline__ void mma16816(float* d, const uint32_t* a, uint32_t b0, uint32_t b1) {
    asm volatile(
        "mma.sync.aligned.m16n8k16.row.col.f32.f16.f16.f32 "
        "{%0,%1,%2,%3}, {%4,%5,%6,%7}, {%8,%9}, {%0,%1,%2,%3};"
        : "+f"(d[0]), "+f"(d[1]), "+f"(d[2]), "+f"(d[3])
        : "r"(a[0]), "r"(a[1]), "r"(a[2]), "r"(a[3]), "r"(b0), "r"(b1));
}
__device__ __forceinline__ void cpa16(uint32_t dst, const void* src) {
    asm volatile("cp.async.ca.shared.global [%0], [%1], 16;" :: "r"(dst), "l"(src) : "memory");
}
__device__ __forceinline__ void cpa_commit() {
    asm volatile("cp.async.commit_group;" ::: "memory");
}
__device__ __forceinline__ void cpa_wait0() {
    asm volatile("cp.async.wait_group 0;" ::: "memory");
}

#define LDSW 40

// ============ GEMM A=fp32 (reduce): C = A @ B^T + bias, writes f32 + f16 ====
#define ARR (128*LDSW)
#define STG (2*ARR)
#define SMEM_G (2*STG*2)

__global__ __launch_bounds__(256)
void mma_gemm(const float* __restrict__ A, const __half* __restrict__ B,
              const float* __restrict__ bias, float* __restrict__ C,
              __half* __restrict__ C16, int M, int N, int Ksrc)
{
    extern __shared__ __half smp[];
    const int tid = threadIdx.x, lane = tid & 31, wid = tid >> 5;
    const int bm = blockIdx.y * 128, bn = blockIdx.x * 128;
    const int wm = (wid & 3) * 32, wn = (wid >> 2) * 64;

    float c[2][8][4];
    #pragma unroll
    for (int i = 0; i < 2; i++)
        #pragma unroll
        for (int j = 0; j < 8; j++)
            #pragma unroll
            for (int q = 0; q < 4; q++) c[i][j][q] = 0.f;

    const int lrow = tid >> 1, lcol = (tid & 1) * 16;
    const bool rv = (bm + lrow) < M;
    const float* Arow = A + (size_t)(bm + lrow) * Ksrc + lcol;
    const __half* Brow = B + (size_t)(bn + lrow) * KP + lcol;

    const uint32_t u0 = smem_u32(smp);
    const int lodst = lrow * LDSW + lcol;
    const uint32_t bdst = u0 + (uint32_t)(ARR + lodst) * 2;

    const int aro = (lane & 7) + ((lane >> 3) & 1) * 8;
    const int ako = ((lane >> 4) & 1) * 8;
    const int bro = (lane & 7) + ((lane >> 4) & 1) * 8;
    const int bko = ((lane >> 3) & 1) * 8;

    {
        #pragma unroll
        for (int q = 0; q < 4; q++) {
            int k = lcol + q * 4;
            float4 v = make_float4(0.f,0.f,0.f,0.f);
            if (rv && k < Ksrc) v = *(const float4*)(Arow + q * 4);
            __half2 p0 = __floats2half2_rn(v.x, v.y);
            __half2 p1 = __floats2half2_rn(v.z, v.w);
            int o = lodst + q * 4;
            *(__half2*)&smp[o] = p0; *(__half2*)&smp[o+2] = p1;
        }
        cpa16(bdst, Brow); cpa16(bdst + 16, Brow + 8);
        cpa_commit();
    }

    for (int ch = 0; ch < 8; ch++) {
        const int cur = ch & 1, nxt = cur ^ 1;
        cpa_wait0();
        __syncthreads();
        float ar[16];
        if (ch < 7) {
            const int kn = (ch + 1) * 32;
            #pragma unroll
            for (int q = 0; q < 4; q++) {
                int k = kn + lcol + q * 4;
                float4 v = make_float4(0.f,0.f,0.f,0.f);
                if (rv && k < Ksrc) v = *(const float4*)(Arow + kn + q * 4);
                ar[q*4+0]=v.x; ar[q*4+1]=v.y; ar[q*4+2]=v.z; ar[q*4+3]=v.w;
            }
            const uint32_t sb = (uint32_t)(nxt * STG) * 2;
            cpa16(bdst + sb, Brow + kn); cpa16(bdst + sb + 16, Brow + kn + 8);
            cpa_commit();
        }
        const uint32_t base = u0 + (uint32_t)(cur * STG) * 2;
        const uint32_t uA = base, uB = base + ARR * 2;
        #pragma unroll
        for (int kh = 0; kh < 2; kh++) {
            const int kb = kh * 16;
            uint32_t ah[2][4];
            #pragma unroll
            for (int mt = 0; mt < 2; mt++)
                ldmx4(ah[mt], uA + (uint32_t)(((wm + mt*16 + aro) * LDSW + kb + ako) * 2));
            #pragma unroll
            for (int ng = 0; ng < 4; ng++) {
                uint32_t bh[4];
                ldmx4(bh, uB + (uint32_t)(((wn + ng*16 + bro) * LDSW + kb + bko) * 2));
                #pragma unroll
                for (int mt = 0; mt < 2; mt++) {
                    mma16816(c[mt][2*ng],   ah[mt], bh[0], bh[1]);
                    mma16816(c[mt][2*ng+1], ah[mt], bh[2], bh[3]);
                }
            }
        }
        if (ch < 7) {
            __half* sA = smp + nxt * STG;
            #pragma unroll
            for (int q = 0; q < 4; q++) {
                __half2 p0 = __floats2half2_rn(ar[q*4+0], ar[q*4+1]);
                __half2 p1 = __floats2half2_rn(ar[q*4+2], ar[q*4+3]);
                int o = lodst + q * 4;
                *(__half2*)&sA[o] = p0; *(__half2*)&sA[o+2] = p1;
            }
        }
    }

    #pragma unroll
    for (int mt = 0; mt < 2; mt++) {
        int row = bm + wm + mt * 16 + (lane >> 2);
        #pragma unroll
        for (int nidx = 0; nidx < 8; nidx++) {
            int col = bn + wn + nidx * 8 + (lane & 3) * 2;
            float b0 = 0.f, b1 = 0.f;
            if (bias) { b0 = bias[col]; b1 = bias[col + 1]; }
            float v00 = c[mt][nidx][0] + b0, v01 = c[mt][nidx][1] + b1;
            float v10 = c[mt][nidx][2] + b0, v11 = c[mt][nidx][3] + b1;
            if (row < M) {
                *(float2*)(C + (size_t)row * N + col) = make_float2(v00, v01);
                *(__half2*)(C16 + (size_t)row * N + col) = __floats2half2_rn(v00, v01);
            }
            if (row + 8 < M) {
                *(float2*)(C + (size_t)(row + 8) * N + col) = make_float2(v10, v11);
                *(__half2*)(C16 + (size_t)(row + 8) * N + col) = __floats2half2_rn(v10, v11);
            }
        }
    }
}

// ============ GEMM A=fp16 (ggc): m16 = A @ B^T (fp16 out), zeroes agg =======
__global__ __launch_bounds__(256)
void mma_gemm16(const __half* __restrict__ A, const __half* __restrict__ B,
                __half* __restrict__ C16, float4* __restrict__ aggz,
                int M, int N)
{
    extern __shared__ __half smp[];
    const int tid = threadIdx.x, lane = tid & 31, wid = tid >> 5;
    const int bm = blockIdx.y * 128, bn = blockIdx.x * 128;
    const int wm = (wid & 3) * 32, wn = (wid >> 2) * 64;

    float c[2][8][4];
    #pragma unroll
    for (int i = 0; i < 2; i++)
        #pragma unroll
        for (int j = 0; j < 8; j++)
            #pragma unroll
            for (int q = 0; q < 4; q++) c[i][j][q] = 0.f;

    const int lrow = tid >> 1, lcol = (tid & 1) * 16;
    const __half* Arow = A + (size_t)(bm + lrow) * KP + lcol;
    const __half* Brow = B + (size_t)(bn + lrow) * KP + lcol;

    const uint32_t u0 = smem_u32(smp);
    const int lodst = lrow * LDSW + lcol;
    const uint32_t adst = u0 + (uint32_t)lodst * 2;
    const uint32_t bdst = u0 + (uint32_t)(ARR + lodst) * 2;

    const int aro = (lane & 7) + ((lane >> 3) & 1) * 8;
    const int ako = ((lane >> 4) & 1) * 8;
    const int bro = (lane & 7) + ((lane >> 4) & 1) * 8;
    const int bko = ((lane >> 3) & 1) * 8;

    cpa16(adst, Arow); cpa16(adst + 16, Arow + 8);
    cpa16(bdst, Brow); cpa16(bdst + 16, Brow + 8);
    cpa_commit();

    // ---- zero a slice of agg (this kernel runs right before scatter) ----
    {
        const int nblk = gridDim.x * gridDim.y;
        const int slice = blockIdx.y * gridDim.x + blockIdx.x;
        const int total4 = NN * HH / 4;
        const int per = (total4 + nblk - 1) / nblk;
        int s0 = slice * per;
        int s1 = min(s0 + per, total4);
        const float4 z = make_float4(0.f,0.f,0.f,0.f);
        for (int i = s0 + tid; i < s1; i += 256) aggz[i] = z;
    }

    for (int ch = 0; ch < 8; ch++) {
        const int cur = ch & 1, nxt = cur ^ 1;
        cpa_wait0();
        __syncthreads();
        if (ch < 7) {
            const int kn = (ch + 1) * 32;
            const uint32_t sb = (uint32_t)(nxt * STG) * 2;
            cpa16(adst + sb, Arow + kn); cpa16(adst + sb + 16, Arow + kn + 8);
            cpa16(bdst + sb, Brow + kn); cpa16(bdst + sb + 16, Brow + kn + 8);
            cpa_commit();
        }
        const uint32_t base = u0 + (uint32_t)(cur * STG) * 2;
        const uint32_t uA = base, uB = base + ARR * 2;
        #pragma unroll
        for (int kh = 0; kh < 2; kh++) {
            const int kb = kh * 16;
            uint32_t ah[2][4];
            #pragma unroll
            for (int mt = 0; mt < 2; mt++)
                ldmx4(ah[mt], uA + (uint32_t)(((wm + mt*16 + aro) * LDSW + kb + ako) * 2));
            #pragma unroll
            for (int ng = 0; ng < 4; ng++) {
                uint32_t bh[4];
                ldmx4(bh, uB + (uint32_t)(((wn + ng*16 + bro) * LDSW + kb + bko) * 2));
                #pragma unroll
                for (int mt = 0; mt < 2; mt++) {
                    mma16816(c[mt][2*ng],   ah[mt], bh[0], bh[1]);
                    mma16816(c[mt][2*ng+1], ah[mt], bh[2], bh[3]);
                }
            }
        }
    }

    #pragma unroll
    for (int mt = 0; mt < 2; mt++) {
        int row = bm + wm + mt * 16 + (lane >> 2);
        #pragma unroll
        for (int nidx = 0; nidx < 8; nidx++) {
            int col = bn + wn + nidx * 8 + (lane & 3) * 2;
            if (row < M)
                *(__half2*)(C16 + (size_t)row * N + col) =
                    __floats2half2_rn(c[mt][nidx][0], c[mt][nidx][1]);
            if (row + 8 < M)
                *(__half2*)(C16 + (size_t)(row + 8) * N + col) =
                    __floats2half2_rn(c[mt][nidx][2], c[mt][nidx][3]);
        }
    }
}

// ============ fused gi+gh GEMM + GRU ========================================
#define ARRA (128*LDSW)
#define ARRW (64*LDSW)
#define STGF (2*ARRA + 6*ARRW)
#define SMEM_F (2*STGF*2)

__global__ __launch_bounds__(256)
void gru_fused(const float* __restrict__ agg32, const __half* __restrict__ h16,
               const float* __restrict__ h32,
               const __half* __restrict__ Wih, const __half* __restrict__ Whh,
               const float* __restrict__ b_ih, const float* __restrict__ b_hh,
               float* __restrict__ h32n, __half* __restrict__ h16n, int M)
{
    extern __shared__ __half smp[];
    const int tid = threadIdx.x, lane = tid & 31, wid = tid >> 5;
    const int bm = blockIdx.y * 128, bn = blockIdx.x * 64;
    const int wm = (wid & 3) * 32, wn = (wid >> 2) * 32;

    float cr[2][4][4], cz[2][4][4], cin[2][4][4], chn[2][4][4];
    #pragma unroll
    for (int mt = 0; mt < 2; mt++)
        #pragma unroll
        for (int f = 0; f < 4; f++)
            #pragma unroll
            for (int q = 0; q < 4; q++)
            { cr[mt][f][q]=0.f; cz[mt][f][q]=0.f; cin[mt][f][q]=0.f; chn[mt][f][q]=0.f; }

    const int arow = tid >> 1, aseg = (tid & 1) * 16;
    const bool rv = (bm + arow) < M;
    const float* pAg = agg32 + (size_t)(bm + arow) * HH + aseg;
    const __half* pAh = h16   + (size_t)(bm + arow) * KP + aseg;
    const int wrow = tid >> 2, wseg = (tid & 3) * 8;
    const __half* pW[6];
    pW[0] = Wih + (size_t)(bn + wrow) * KP + wseg;
    pW[1] = Whh + (size_t)(bn + wrow) * KP + wseg;
    pW[2] = Wih + (size_t)(256 + bn + wrow) * KP + wseg;
    pW[3] = Whh + (size_t)(256 + bn + wrow) * KP + wseg;
    pW[4] = Wih + (size_t)(512 + bn + wrow) * KP + wseg;
    pW[5] = Whh + (size_t)(512 + bn + wrow) * KP + wseg;

    const uint32_t u0 = smem_u32(smp);
    const int aodst = arow * LDSW + aseg;
    const uint32_t ahdst = u0 + (uint32_t)(ARRA + aodst) * 2;
    const uint32_t wdst0 = u0 + (uint32_t)(2*ARRA + wrow * LDSW + wseg) * 2;

    const int aro = (lane & 7) + ((lane >> 3) & 1) * 8;
    const int ako = ((lane >> 4) & 1) * 8;
    const int bro = (lane & 7) + ((lane >> 4) & 1) * 8;
    const int bko = ((lane >> 3) & 1) * 8;

    {
        #pragma unroll
        for (int q = 0; q < 4; q++) {
            float4 v = rv ? *(const float4*)(pAg + q * 4) : make_float4(0.f,0.f,0.f,0.f);
            __half2 p0 = __floats2half2_rn(v.x, v.y);
            __half2 p1 = __floats2half2_rn(v.z, v.w);
            int o = aodst + q * 4;
            *(__half2*)&smp[o] = p0; *(__half2*)&smp[o+2] = p1;
        }
        cpa16(ahdst, pAh); cpa16(ahdst + 16, pAh + 8);
        #pragma unroll
        for (int s = 0; s < 6; s++)
            cpa16(wdst0 + (uint32_t)(s * ARRW) * 2, pW[s]);
        cpa_commit();
    }

    for (int ch = 0; ch < 8; ch++) {
        const int cur = ch & 1, nxt = cur ^ 1;
        cpa_wait0();
        __syncthreads();
        float ar[16];
        if (ch < 7) {
            const int kn = (ch + 1) * 32;
            #pragma unroll
            for (int q = 0; q < 4; q++) {
                float4 v = rv ? *(const float4*)(pAg + kn + q * 4) : make_float4(0.f,0.f,0.f,0.f);
                ar[q*4+0]=v.x; ar[q*4+1]=v.y; ar[q*4+2]=v.z; ar[q*4+3]=v.w;
            }
            const uint32_t sb = (uint32_t)(nxt * STGF) * 2;
            cpa16(ahdst + sb, pAh + kn); cpa16(ahdst + sb + 16, pAh + kn + 8);
            #pragma unroll
            for (int s = 0; s < 6; s++)
                cpa16(wdst0 + sb + (uint32_t)(s * ARRW) * 2, pW[s] + kn);
            cpa_commit();
        }

        const uint32_t base = u0 + (uint32_t)(cur * STGF) * 2;
        const uint32_t uAg = base, uAh = base + (uint32_t)ARRA * 2;
        #pragma unroll
        for (int kh = 0; kh < 2; kh++) {
            const int kb = kh * 16;
            uint32_t ag[2][4], ah[2][4];
            #pragma unroll
            for (int mt = 0; mt < 2; mt++) {
                const uint32_t ao = (uint32_t)(((wm + mt*16 + aro) * LDSW + kb + ako) * 2);
                ldmx4(ag[mt], uAg + ao);
                ldmx4(ah[mt], uAh + ao);
            }
            #pragma unroll
            for (int ng = 0; ng < 2; ng++) {
                const uint32_t bo = (uint32_t)(((wn + ng*16 + bro) * LDSW + kb + bko) * 2);
                uint32_t bb[4];
                ldmx4(bb, base + (uint32_t)(2*ARRA + 0*ARRW) * 2 + bo);
                #pragma unroll
                for (int mt = 0; mt < 2; mt++) {
                    mma16816(cr[mt][2*ng],   ag[mt], bb[0], bb[1]);
                    mma16816(cr[mt][2*ng+1], ag[mt], bb[2], bb[3]);
                }
                ldmx4(bb, base + (uint32_t)(2*ARRA + 1*ARRW) * 2 + bo);
                #pragma unroll
                for (int mt = 0; mt < 2; mt++) {
                    mma16816(cr[mt][2*ng],   ah[mt], bb[0], bb[1]);
                    mma16816(cr[mt][2*ng+1], ah[mt], bb[2], bb[3]);
                }
                ldmx4(bb, base + (uint32_t)(2*ARRA + 2*ARRW) * 2 + bo);
                #pragma unroll
                for (int mt = 0; mt < 2; mt++) {
                    mma16816(cz[mt][2*ng],   ag[mt], bb[0], bb[1]);
                    mma16816(cz[mt][2*ng+1], ag[mt], bb[2], bb[3]);
                }
                ldmx4(bb, base + (uint32_t)(2*ARRA + 3*ARRW) * 2 + bo);
                #pragma unroll
                for (int mt = 0; mt < 2; mt++) {
                    mma16816(cz[mt][2*ng],   ah[mt], bb[0], bb[1]);
                    mma16816(cz[mt][2*ng+1], ah[mt], bb[2], bb[3]);
                }
                ldmx4(bb, base + (uint32_t)(2*ARRA + 4*ARRW) * 2 + bo);
                #pragma unroll
                for (int mt = 0; mt < 2; mt++) {
                    mma16816(cin[mt][2*ng],   ag[mt], bb[0], bb[1]);
                    mma16816(cin[mt][2*ng+1], ag[mt], bb[2], bb[3]);
                }
                ldmx4(bb, base + (uint32_t)(2*ARRA + 5*ARRW) * 2 + bo);
                #pragma unroll
                for (int mt = 0; mt < 2; mt++) {
                    mma16816(chn[mt][2*ng],   ah[mt], bb[0], bb[1]);
                    mma16816(chn[mt][2*ng+1], ah[mt], bb[2], bb[3]);
                }
            }
        }

        if (ch < 7) {
            __half* sA = smp + nxt * STGF;
            #pragma unroll
            for (int q = 0; q < 4; q++) {
                __half2 p0 = __floats2half2_rn(ar[q*4+0], ar[q*4+1]);
                __half2 p1 = __floats2half2_rn(ar[q*4+2], ar[q*4+3]);
                int o = aodst + q * 4;
                *(__half2*)&sA[o] = p0; *(__half2*)&sA[o+2] = p1;
            }
        }
    }

    #pragma unroll
    for (int mt = 0; mt < 2; mt++) {
        const int r0 = bm + wm + mt * 16 + (lane >> 2);
        #pragma unroll
        for (int f = 0; f < 4; f++) {
            const int col = bn + wn + f * 8 + (lane & 3) * 2;
            const float br0 = __ldg(b_ih + col)       + __ldg(b_hh + col);
            const float br1 = __ldg(b_ih + col + 1)   + __ldg(b_hh + col + 1);
            const float bz0 = __ldg(b_ih + 256 + col) + __ldg(b_hh + 256 + col);
            const float bz1 = __ldg(b_ih + 257 + col) + __ldg(b_hh + 257 + col);
            const float bin0 = __ldg(b_ih + 512 + col),   bin1 = __ldg(b_ih + 513 + col);
            const float bhn0 = __ldg(b_hh + 512 + col),   bhn1 = __ldg(b_hh + 513 + col);
            #pragma unroll
            for (int e = 0; e < 2; e++) {
                const int row = r0 + e * 8;
                if (row >= M) continue;
                float2 hv = *(const float2*)(h32 + (size_t)row * HH + col);
                float rr0 = 1.f / (1.f + __expf(-(cr[mt][f][2*e]   + br0)));
                float rr1 = 1.f / (1.f + __expf(-(cr[mt][f][2*e+1] + br1)));
                float zz0 = 1.f / (1.f + __expf(-(cz[mt][f][2*e]   + bz0)));
                float zz1 = 1.f / (1.f + __expf(-(cz[mt][f][2*e+1] + bz1)));
                float nn0 = tanhf(cin[mt][f][2*e]   + bin0 + rr0 * (chn[mt][f][2*e]   + bhn0));
                float nn1 = tanhf(cin[mt][f][2*e+1] + bin1 + rr1 * (chn[mt][f][2*e+1] + bhn1));
                float o0 = (1.f - zz0) * nn0 + zz0 * hv.x;
                float o1 = (1.f - zz1) * nn1 + zz1 * hv.y;
                *(float2*)(h32n + (size_t)row * HH + col) = make_float2(o0, o1);
                *(__half2*)(h16n + (size_t)row * HH + col) = __floats2half2_rn(o0, o1);
            }
        }
    }
}

// ---------------- scatter: agg[dst] += m16[src] (fp16 read, fp32 atomics) ---
__global__ void scatter_kernel(const __half* __restrict__ m16,
                               const int* __restrict__ src,
                               const int* __restrict__ dst,
                               float* __restrict__ agg)
{
    long long t = (long long)blockIdx.x * blockDim.x + threadIdx.x;
    int e = (int)(t >> 6);
    if (e >= NE) return;
    int c = ((int)t & 63) << 2;
    int s = __ldg(src + e);
    int d = __ldg(dst + e);
    uint2 raw = *(const uint2*)(m16 + (size_t)s * HH + c);
    __half2 h0 = *(__half2*)&raw.x;
    __half2 h1 = *(__half2*)&raw.y;
    float2 f0 = __half22float2(h0);
    float2 f1 = __half22float2(h1);
    float* p = agg + (size_t)d * HH + c;
    asm volatile("red.global.add.v4.f32 [%0], {%1,%2,%3,%4};"
                 :: "l"(p), "f"(f0.x), "f"(f0.y), "f"(f1.x), "f"(f1.y) : "memory");
}

// ---------------- head -------------------------------------------------------
__global__ void head_kernel(const float* __restrict__ h,
                            const float* __restrict__ W_lin,
                            const float* __restrict__ b_lin,
                            float* __restrict__ out)
{
    int gw = (blockIdx.x * blockDim.x + threadIdx.x) >> 5;
    int lane = threadIdx.x & 31;
    if (gw >= NN) return;
    const float* hr = h + (size_t)gw * HH;
    float a0 = 0.f, a1 = 0.f;
    #pragma unroll
    for (int k = lane; k < HH; k += 32) {
        float v = hr[k];
        v = v > 0.f ? v : 0.f;
        a0 += v * __ldg(W_lin + k);
        a1 += v * __ldg(W_lin + HH + k);
    }
    #pragma unroll
    for (int off = 16; off; off >>= 1) {
        a0 += __shfl_xor_sync(0xffffffffu, a0, off);
        a1 += __shfl_xor_sync(0xffffffffu, a1, off);
    }
    if (lane == 0) {
        float o0 = a0 + b_lin[0];
        float o1 = a1 + b_lin[1];
        float mx = fmaxf(o0, o1);
        float lse = mx + logf(expf(o0 - mx) + expf(o1 - mx));
        out[2*gw]     = o0 - lse;
        out[2*gw + 1] = o1 - lse;
    }
}

// ---------------- launch -----------------------------------------------------
extern "C" void kernel_launch(void* const* d_in, const int* in_sizes, int n_in,
                              void* d_out, int out_size)
{
    const float* x        = (const float*)d_in[0];
    const int*   edge     = (const int*)  d_in[1];
    const float* W_reduce = (const float*)d_in[3];
    const float* b_reduce = (const float*)d_in[4];
    const float* W_ggc    = (const float*)d_in[5];
    const float* W_ih     = (const float*)d_in[6];
    const float* W_hh     = (const float*)d_in[7];
    const float* b_ih     = (const float*)d_in[8];
    const float* b_hh     = (const float*)d_in[9];
    const float* W_lin    = (const float*)d_in[10];
    const float* b_lin    = (const float*)d_in[11];
    float* out = (float*)d_out;

    const int* src = edge;
    const int* dst = edge + NE;

    float *h0, *h1, *agg;
    __half *m16, *h16a, *h16b, *wred, *wggc, *wih, *whh;
    cudaGetSymbolAddress((void**)&h0,    g_h0);
    cudaGetSymbolAddress((void**)&h1,    g_h1);
    cudaGetSymbolAddress((void**)&agg,   g_agg);
    cudaGetSymbolAddress((void**)&m16,   g_m16);
    cudaGetSymbolAddress((void**)&h16a,  g_h16a);
    cudaGetSymbolAddress((void**)&h16b,  g_h16b);
    cudaGetSymbolAddress((void**)&wred,  g_wred);
    cudaGetSymbolAddress((void**)&wggc,  g_wggc);
    cudaGetSymbolAddress((void**)&wih,   g_wih);
    cudaGetSymbolAddress((void**)&whh,   g_whh);

    cudaFuncSetAttribute(mma_gemm,   cudaFuncAttributeMaxDynamicSharedMemorySize, SMEM_G);
    cudaFuncSetAttribute(mma_gemm16, cudaFuncAttributeMaxDynamicSharedMemorySize, SMEM_G);
    cudaFuncSetAttribute(gru_fused,  cudaFuncAttributeMaxDynamicSharedMemorySize, SMEM_F);

    conv_w<<<(HH*KP + 255)/256, 256>>>(W_reduce, wred, HH, 200);
    conv_w<<<(H3*KP + 255)/256, 256>>>(W_ih, wih, H3, KP);
    conv_w<<<(H3*KP + 255)/256, 256>>>(W_hh, whh, H3, KP);
    conv_wggcT<<<(8*HH*KP + 255)/256, 256>>>(W_ggc, wggc);

    const int mtiles128 = (NN + 127) / 128;   // 391

    mma_gemm<<<dim3(HH/128, mtiles128), 256, SMEM_G>>>(x, wred, b_reduce, h0, h16a, NN, HH, 200);

    float *hc32 = h0, *hn32 = h1;
    __half *hc16 = h16a, *hn16 = h16b;
    for (int s = 0; s < 8; s++) {
        mma_gemm16<<<dim3(HH/128, mtiles128), 256, SMEM_G>>>(hc16, wggc + (size_t)s*HH*KP,
                                                             m16, (float4*)agg, NN, HH);
        scatter_kernel<<<((long long)NE*64 + 255)/256, 256>>>(m16, src, dst, agg);
        gru_fused<<<dim3(HH/64, mtiles128), 256, SMEM_F>>>(agg, hc16, hc32, wih, whh,
                                                           b_ih, b_hh, hn32, hn16, NN);
        { float* t = hc32; hc32 = hn32; hn32 = t; }
        { __half* t = hc16; hc16 = hn16; hn16 = t; }
    }

    head_kernel<<<(NN*32 + 255)/256, 256>>>(hc32, W_lin, b_lin, out);
}